// round 1
// baseline (speedup 1.0000x reference)
#include <cuda_runtime.h>
#include <math.h>

// Problem dims (fixed)
#define BD 16
#define PD 2048
#define QD 2048
#define DD 1024
#define HD 1024

// Scratch (allocation-free: __device__ globals)
__device__ float g_Wp[(size_t)BD * PD * HD];          // 134 MB
__device__ float g_Wq[(size_t)BD * QD * HD];          // 134 MB
__device__ float g_S [(size_t)BD * PD * QD];          // 268 MB
__device__ float g_O [(size_t)BD * PD * HD];          // 134 MB

// ----------------------------------------------------------------------------
// Tiled fp32 SGEMM: C[M,N] = A[M,K] * B(+bias)(+relu)
//   TB=false: B is row-major [K,N]  (NN)
//   TB=true : B is row-major [N,K], contracted over its columns (NT, i.e. A*B^T)
// Batched via blockIdx.z with element strides.
// Requires M%128==0, N%128==0, K%16==0 (true for all shapes here).
// ----------------------------------------------------------------------------
template <bool TB, bool BIAS, bool RELU>
__global__ void __launch_bounds__(256, 2) sgemm_kernel(
    const float* __restrict__ A, const float* __restrict__ B,
    const float* __restrict__ bias, float* __restrict__ C,
    int M, int N, int K,
    size_t strideA, size_t strideB, size_t strideC)
{
    const int bm = blockIdx.y * 128;
    const int bn = blockIdx.x * 128;
    A += (size_t)blockIdx.z * strideA;
    B += (size_t)blockIdx.z * strideB;
    C += (size_t)blockIdx.z * strideC;

    const int lda = K;
    const int ldb = TB ? K : N;
    const int ldc = N;

    __shared__ float As[16][128];   // [k][m]
    __shared__ float Bs[16][128];   // [k][n]

    const int tid = threadIdx.x;
    const int tx = tid & 15;        // 0..15 -> 8 cols each
    const int ty = tid >> 4;        // 0..15 -> 8 rows each

    float acc[8][8];
#pragma unroll
    for (int i = 0; i < 8; i++)
#pragma unroll
        for (int j = 0; j < 8; j++) acc[i][j] = 0.f;

    for (int k0 = 0; k0 < K; k0 += 16) {
        // ---- load A tile [128 x 16], store transposed As[k][m]
#pragma unroll
        for (int r = 0; r < 2; r++) {
            int idx = tid + r * 256;            // 0..511
            int k4  = (idx & 3) * 4;            // 0,4,8,12
            int m   = idx >> 2;                 // 0..127
            float4 v = *(const float4*)(A + (size_t)(bm + m) * lda + k0 + k4);
            As[k4 + 0][m] = v.x;
            As[k4 + 1][m] = v.y;
            As[k4 + 2][m] = v.z;
            As[k4 + 3][m] = v.w;
        }
        // ---- load B tile -> Bs[k][n]
        if (TB) {
#pragma unroll
            for (int r = 0; r < 2; r++) {
                int idx = tid + r * 256;
                int k4  = (idx & 3) * 4;
                int n   = idx >> 2;
                float4 v = *(const float4*)(B + (size_t)(bn + n) * ldb + k0 + k4);
                Bs[k4 + 0][n] = v.x;
                Bs[k4 + 1][n] = v.y;
                Bs[k4 + 2][n] = v.z;
                Bs[k4 + 3][n] = v.w;
            }
        } else {
#pragma unroll
            for (int r = 0; r < 2; r++) {
                int idx = tid + r * 256;
                int n4  = (idx & 31) * 4;       // 0..124
                int k   = idx >> 5;             // 0..15
                *(float4*)&Bs[k][n4] =
                    *(const float4*)(B + (size_t)(k0 + k) * ldb + bn + n4);
            }
        }
        __syncthreads();

#pragma unroll
        for (int kk = 0; kk < 16; kk++) {
            float a[8], b[8];
            *(float4*)&a[0] = *(const float4*)&As[kk][ty * 8];
            *(float4*)&a[4] = *(const float4*)&As[kk][ty * 8 + 4];
            *(float4*)&b[0] = *(const float4*)&Bs[kk][tx * 8];
            *(float4*)&b[4] = *(const float4*)&Bs[kk][tx * 8 + 4];
#pragma unroll
            for (int i = 0; i < 8; i++)
#pragma unroll
                for (int j = 0; j < 8; j++)
                    acc[i][j] = fmaf(a[i], b[j], acc[i][j]);
        }
        __syncthreads();
    }

    // ---- epilogue
#pragma unroll
    for (int i = 0; i < 8; i++) {
        int row = bm + ty * 8 + i;
#pragma unroll
        for (int j = 0; j < 8; j += 4) {
            int col = bn + tx * 8 + j;
            float4 v;
            v.x = acc[i][j + 0];
            v.y = acc[i][j + 1];
            v.z = acc[i][j + 2];
            v.w = acc[i][j + 3];
            if (BIAS) {
                v.x += bias[col + 0];
                v.y += bias[col + 1];
                v.z += bias[col + 2];
                v.w += bias[col + 3];
            }
            if (RELU) {
                v.x = fmaxf(v.x, 0.f);
                v.y = fmaxf(v.y, 0.f);
                v.z = fmaxf(v.z, 0.f);
                v.w = fmaxf(v.w, 0.f);
            }
            *(float4*)(C + (size_t)row * ldc + col) = v;
        }
    }
}

// ----------------------------------------------------------------------------
// Masked softmax over rows of S[B*P, Q] in place.
// Semantics match the reference (softmax(s*mask)*mask renormalized):
//   alpha_q = mask_q * exp(s_q - m) / sum_masked exp(s - m),  m = max over masked
// (the eps term is O(1e-13) relative — below tolerance)
// One 256-thread block per row, 8 elements per thread.
// ----------------------------------------------------------------------------
__global__ void __launch_bounds__(256) softmax_kernel(
    float* __restrict__ S, const int* __restrict__ qmask)
{
    const size_t row = blockIdx.x;          // 0 .. B*P-1
    const int b = (int)(row / PD);
    float* s = S + row * QD;
    const int* mask = qmask + (size_t)b * QD;

    __shared__ float red[256];
    const int tid = threadIdx.x;

    float vals[8];
    int   mk[8];
    float m = -INFINITY;
#pragma unroll
    for (int i = 0; i < 8; i++) {
        int q = tid + i * 256;
        vals[i] = s[q];
        mk[i]   = mask[q];
        if (mk[i]) m = fmaxf(m, vals[i]);
    }
    red[tid] = m;
    __syncthreads();
    for (int st = 128; st > 0; st >>= 1) {
        if (tid < st) red[tid] = fmaxf(red[tid], red[tid + st]);
        __syncthreads();
    }
    m = red[0];
    __syncthreads();

    float sum = 0.f;
#pragma unroll
    for (int i = 0; i < 8; i++) {
        float e = mk[i] ? expf(vals[i] - m) : 0.f;
        vals[i] = e;
        sum += e;
    }
    red[tid] = sum;
    __syncthreads();
    for (int st = 128; st > 0; st >>= 1) {
        if (tid < st) red[tid] += red[tid + st];
        __syncthreads();
    }
    sum = red[0];

    const float inv = (sum > 0.f) ? (1.f / sum) : 0.f;  // all-masked row -> zeros
#pragma unroll
    for (int i = 0; i < 8; i++) {
        int q = tid + i * 256;
        s[q] = vals[i] * inv;
    }
}

// ----------------------------------------------------------------------------
extern "C" void kernel_launch(void* const* d_in, const int* in_sizes, int n_in,
                              void* d_out, int out_size)
{
    const float* passage  = (const float*)d_in[0];  // [B,P,D]
    const float* question = (const float*)d_in[1];  // [B,Q,D]
    const int*   q_mask   = (const int*)  d_in[2];  // [B,Q]
    const float* W_w      = (const float*)d_in[3];  // [D,H]
    const float* W_b      = (const float*)d_in[4];  // [H]
    const float* map_w    = (const float*)d_in[5];  // [H,H]
    const float* map_b    = (const float*)d_in[6];  // [H]
    float* out = (float*)d_out;                     // [B,P,H]

    float *Wp, *Wq, *S, *O;
    cudaGetSymbolAddress((void**)&Wp, g_Wp);
    cudaGetSymbolAddress((void**)&Wq, g_Wq);
    cudaGetSymbolAddress((void**)&S,  g_S);
    cudaGetSymbolAddress((void**)&O,  g_O);

    dim3 blk(256);

    // Wp = passage @ W_w + W_b   [B*P, H]
    sgemm_kernel<false, true, false><<<dim3(HD / 128, (BD * PD) / 128, 1), blk>>>(
        passage, W_w, W_b, Wp, BD * PD, HD, DD, 0, 0, 0);

    // Wq = question @ W_w + W_b  [B*Q, H]
    sgemm_kernel<false, true, false><<<dim3(HD / 128, (BD * QD) / 128, 1), blk>>>(
        question, W_w, W_b, Wq, BD * QD, HD, DD, 0, 0, 0);

    // S[b] = Wp[b] @ Wq[b]^T     [P, Q] per batch
    sgemm_kernel<true, false, false><<<dim3(QD / 128, PD / 128, BD), blk>>>(
        Wp, Wq, nullptr, S, PD, QD, HD,
        (size_t)PD * HD, (size_t)QD * HD, (size_t)PD * QD);

    // masked softmax over Q, in place
    softmax_kernel<<<BD * PD, 256>>>(S, q_mask);

    // O[b] = alpha[b] @ Wq[b]    [P, H] per batch
    sgemm_kernel<false, false, false><<<dim3(HD / 128, PD / 128, BD), blk>>>(
        S, Wq, nullptr, O, PD, HD, QD,
        (size_t)PD * QD, (size_t)QD * HD, (size_t)PD * HD);

    // out = relu(O @ map_w + map_b)  [B*P, H]
    sgemm_kernel<false, true, true><<<dim3(HD / 128, (BD * PD) / 128, 1), blk>>>(
        O, map_w, map_b, out, BD * PD, HD, DD, 0, 0, 0);
}

// round 3
// speedup vs baseline: 2.3226x; 2.3226x over previous
#include <cuda_runtime.h>
#include <cuda_fp16.h>
#include <math.h>
#include <stdint.h>

// Problem dims (fixed)
#define BD 16
#define PD 2048
#define QD 2048
#define DD 1024
#define HD 1024
#define BP (BD * PD)   // 32768

// ---------------------------------------------------------------------------
// Scratch (allocation-free: __device__ globals), all split-fp16 pairs + fp32 S
// ---------------------------------------------------------------------------
__device__ __half g_pass_h [(size_t)BP * DD];
__device__ __half g_pass_l [(size_t)BP * DD];
__device__ __half g_ques_h [(size_t)BD * QD * DD];
__device__ __half g_ques_l [(size_t)BD * QD * DD];
__device__ __half g_Wt_h   [(size_t)HD * DD];     // W_w^T
__device__ __half g_Wt_l   [(size_t)HD * DD];
__device__ __half g_mT_h   [(size_t)HD * HD];     // map_w^T
__device__ __half g_mT_l   [(size_t)HD * HD];
__device__ __half g_Wp_h   [(size_t)BP * HD];
__device__ __half g_Wp_l   [(size_t)BP * HD];
__device__ __half g_Wq_h   [(size_t)BD * QD * HD];
__device__ __half g_Wq_l   [(size_t)BD * QD * HD];
__device__ __half g_WqT_h  [(size_t)BD * HD * QD];
__device__ __half g_WqT_l  [(size_t)BD * HD * QD];
__device__ float  g_S      [(size_t)BD * PD * QD];   // 268 MB
__device__ __half g_al_h   [(size_t)BD * PD * QD];   // alpha split
__device__ __half g_al_l   [(size_t)BD * PD * QD];
__device__ __half g_O_h    [(size_t)BP * HD];
__device__ __half g_O_l    [(size_t)BP * HD];

// ---------------------------------------------------------------------------
// PTX helpers (all Ampere-era: no arch-suffix gating)
// ---------------------------------------------------------------------------
__device__ __forceinline__ uint32_t smem_u32(const void* p) {
    uint32_t a;
    asm("{ .reg .u64 t; cvta.to.shared.u64 t, %1; cvt.u32.u64 %0, t; }"
        : "=r"(a) : "l"(p));
    return a;
}

__device__ __forceinline__ void cp_async16(uint32_t dst, const void* src) {
    asm volatile("cp.async.cg.shared.global [%0], [%1], 16;"
                 :: "r"(dst), "l"(src));
}
#define CP_COMMIT() asm volatile("cp.async.commit_group;")
#define CP_WAIT2()  asm volatile("cp.async.wait_group 2;")
#define CP_WAIT0()  asm volatile("cp.async.wait_group 0;")

__device__ __forceinline__ void ldsm4(uint32_t& r0, uint32_t& r1,
                                      uint32_t& r2, uint32_t& r3, uint32_t addr) {
    asm volatile("ldmatrix.sync.aligned.m8n8.x4.shared.b16 {%0,%1,%2,%3}, [%4];"
                 : "=r"(r0), "=r"(r1), "=r"(r2), "=r"(r3) : "r"(addr));
}

__device__ __forceinline__ void mma16816(float c[4], const uint32_t a[4],
                                         uint32_t b0, uint32_t b1) {
    asm volatile(
        "mma.sync.aligned.m16n8k16.row.col.f32.f16.f16.f32 "
        "{%0,%1,%2,%3}, {%4,%5,%6,%7}, {%8,%9}, {%0,%1,%2,%3};"
        : "+f"(c[0]), "+f"(c[1]), "+f"(c[2]), "+f"(c[3])
        : "r"(a[0]), "r"(a[1]), "r"(a[2]), "r"(a[3]), "r"(b0), "r"(b1));
}

// ---------------------------------------------------------------------------
// HGEMM (3xFP16 split):  C[M,N] = A[M,K] * B[N,K]^T  (NT, both K-major fp16 pairs)
// Tile 128x128x32, 256 threads (2x4 warps of 64x32), 4-stage cp.async pipeline.
// Requires M%128==0, N%128==0, K%32==0. Batched via blockIdx.z.
// SMEM rows padded to 80B (5*16B) -> conflict-free ldmatrix without XOR.
// ---------------------------------------------------------------------------
#define TILE_B   10240          // 128 rows * 80 B
#define STAGE_B  40960          // Ah, Al, Bh, Bl
#define NSTAGE   4
#define GEMM_SMEM (STAGE_B * NSTAGE)   // 163840

__device__ __forceinline__ void stage_load(
    uint32_t sbase, const __half* Ahb, const __half* Alb,
    const __half* Bhb, const __half* Blb, int kb, int K, int tid)
{
#pragma unroll
    for (int u = 0; u < 8; u++) {
        int i = tid + u * 256;
        int t = i >> 9;                 // 0..3 : Ah, Al, Bh, Bl
        int r = (i >> 2) & 127;
        int c = i & 3;
        const __half* src =
            (t == 0 ? Ahb : t == 1 ? Alb : t == 2 ? Bhb : Blb)
            + (size_t)r * K + kb * 32 + c * 8;
        uint32_t dst = sbase + t * TILE_B + r * 80 + c * 16;
        cp_async16(dst, src);
    }
}

template <bool SPLIT_OUT, bool BIAS, bool RELU>
__global__ void __launch_bounds__(256, 1) hgemm_kernel(
    const __half* __restrict__ Ah, const __half* __restrict__ Al,
    const __half* __restrict__ Bh, const __half* __restrict__ Bl,
    const float* __restrict__ bias,
    float* __restrict__ Cf, __half* __restrict__ Ch, __half* __restrict__ Cl,
    int K, int N, size_t sA, size_t sB, size_t sC)
{
    extern __shared__ char smem[];
    const uint32_t smem_base = smem_u32(smem);

    const int tid  = threadIdx.x;
    const int lane = tid & 31;
    const int wid  = tid >> 5;
    const int wm   = wid >> 2;          // 0..1
    const int wn   = wid & 3;           // 0..3
    const int bm   = blockIdx.y * 128;
    const int bn   = blockIdx.x * 128;

    const __half* Ahb = Ah + (size_t)blockIdx.z * sA + (size_t)bm * K;
    const __half* Alb = Al + (size_t)blockIdx.z * sA + (size_t)bm * K;
    const __half* Bhb = Bh + (size_t)blockIdx.z * sB + (size_t)bn * K;
    const __half* Blb = Bl + (size_t)blockIdx.z * sB + (size_t)bn * K;

    float acc[4][4][4];
#pragma unroll
    for (int i = 0; i < 4; i++)
#pragma unroll
        for (int j = 0; j < 4; j++)
#pragma unroll
            for (int r = 0; r < 4; r++) acc[i][j][r] = 0.f;

    const int nk = K / 32;

    // prologue: stages 0..2
#pragma unroll
    for (int s = 0; s < NSTAGE - 1; s++) {
        stage_load(smem_base + s * STAGE_B, Ahb, Alb, Bhb, Blb, s, K, tid);
        CP_COMMIT();
    }

    // lane-invariant fragment offsets
    const uint32_t a_off = (uint32_t)((wm * 64 + (lane & 15)) * 80 + (lane >> 4) * 16);
    const int q = lane >> 3;
    const uint32_t b_off = (uint32_t)((wn * 32 + (q >> 1) * 8 + (lane & 7)) * 80
                                      + (q & 1) * 16);

    for (int kb = 0; kb < nk; kb++) {
        CP_WAIT2();
        __syncthreads();

        if (kb + NSTAGE - 1 < nk)
            stage_load(smem_base + ((kb + NSTAGE - 1) & (NSTAGE - 1)) * STAGE_B,
                       Ahb, Alb, Bhb, Blb, kb + NSTAGE - 1, K, tid);
        CP_COMMIT();

        const uint32_t sb = smem_base + (kb & (NSTAGE - 1)) * STAGE_B;
        const uint32_t sa_h = sb;
        const uint32_t sa_l = sb + TILE_B;
        const uint32_t sb_h = sb + 2 * TILE_B;
        const uint32_t sb_l = sb + 3 * TILE_B;

#pragma unroll
        for (int kk = 0; kk < 2; kk++) {
            uint32_t ah[4][4], alr[4][4];
#pragma unroll
            for (int i = 0; i < 4; i++) {
                ldsm4(ah[i][0], ah[i][1], ah[i][2], ah[i][3],
                      sa_h + a_off + i * 1280 + kk * 32);
                ldsm4(alr[i][0], alr[i][1], alr[i][2], alr[i][3],
                      sa_l + a_off + i * 1280 + kk * 32);
            }
            uint32_t bh[4][2], bl[4][2];
#pragma unroll
            for (int jp = 0; jp < 4; jp += 2) {
                ldsm4(bh[jp][0], bh[jp][1], bh[jp + 1][0], bh[jp + 1][1],
                      sb_h + b_off + jp * 640 + kk * 32);
                ldsm4(bl[jp][0], bl[jp][1], bl[jp + 1][0], bl[jp + 1][1],
                      sb_l + b_off + jp * 640 + kk * 32);
            }
#pragma unroll
            for (int i = 0; i < 4; i++)
#pragma unroll
                for (int j = 0; j < 4; j++) {
                    mma16816(acc[i][j], ah[i],  bh[j][0], bh[j][1]);
                    mma16816(acc[i][j], ah[i],  bl[j][0], bl[j][1]);
                    mma16816(acc[i][j], alr[i], bh[j][0], bh[j][1]);
                }
        }
    }

    // ---- epilogue
    CP_WAIT0();
#pragma unroll
    for (int i = 0; i < 4; i++) {
        const int row0 = bm + wm * 64 + i * 16 + (lane >> 2);
        const size_t b0 = (size_t)blockIdx.z * sC + (size_t)row0 * N;
        const size_t b1 = b0 + (size_t)8 * N;
#pragma unroll
        for (int j = 0; j < 4; j++) {
            const int col = bn + wn * 32 + j * 8 + 2 * (lane & 3);
            float c0 = acc[i][j][0], c1 = acc[i][j][1];
            float c2 = acc[i][j][2], c3 = acc[i][j][3];
            if (BIAS) {
                const float bb0 = bias[col], bb1 = bias[col + 1];
                c0 += bb0; c1 += bb1; c2 += bb0; c3 += bb1;
            }
            if (RELU) {
                c0 = fmaxf(c0, 0.f); c1 = fmaxf(c1, 0.f);
                c2 = fmaxf(c2, 0.f); c3 = fmaxf(c3, 0.f);
            }
            if (SPLIT_OUT) {
                __half h0 = __float2half_rn(c0), h1 = __float2half_rn(c1);
                __half h2 = __float2half_rn(c2), h3 = __float2half_rn(c3);
                __half l0 = __float2half_rn(c0 - __half2float(h0));
                __half l1 = __float2half_rn(c1 - __half2float(h1));
                __half l2 = __float2half_rn(c2 - __half2float(h2));
                __half l3 = __float2half_rn(c3 - __half2float(h3));
                *(__half2*)(Ch + b0 + col) = __halves2half2(h0, h1);
                *(__half2*)(Ch + b1 + col) = __halves2half2(h2, h3);
                *(__half2*)(Cl + b0 + col) = __halves2half2(l0, l1);
                *(__half2*)(Cl + b1 + col) = __halves2half2(l2, l3);
            } else {
                *(float2*)(Cf + b0 + col) = make_float2(c0, c1);
                *(float2*)(Cf + b1 + col) = make_float2(c2, c3);
            }
        }
    }
}

// ---------------------------------------------------------------------------
// Elementwise fp32 -> (hi, lo) fp16 split. n must be divisible by 1024.
// ---------------------------------------------------------------------------
__global__ void __launch_bounds__(256) split_kernel(
    const float* __restrict__ in, __half* __restrict__ oh,
    __half* __restrict__ ol)
{
    const size_t idx = (size_t)blockIdx.x * 256 + threadIdx.x;
    float4 v = ((const float4*)in)[idx];
    __half h0 = __float2half_rn(v.x), h1 = __float2half_rn(v.y);
    __half h2 = __float2half_rn(v.z), h3 = __float2half_rn(v.w);
    __half l0 = __float2half_rn(v.x - __half2float(h0));
    __half l1 = __float2half_rn(v.y - __half2float(h1));
    __half l2 = __float2half_rn(v.z - __half2float(h2));
    __half l3 = __float2half_rn(v.w - __half2float(h3));
    ((__half2*)oh)[idx * 2]     = __halves2half2(h0, h1);
    ((__half2*)oh)[idx * 2 + 1] = __halves2half2(h2, h3);
    ((__half2*)ol)[idx * 2]     = __halves2half2(l0, l1);
    ((__half2*)ol)[idx * 2 + 1] = __halves2half2(l2, l3);
}

// ---------------------------------------------------------------------------
// Transpose + split: fp32 in[R][C] -> oh/ol [C][R] fp16
// ---------------------------------------------------------------------------
__global__ void __launch_bounds__(256) transpose_split_kernel(
    const float* __restrict__ in, __half* __restrict__ oh,
    __half* __restrict__ ol, int R, int C)
{
    __shared__ float t[32][33];
    const int c0 = blockIdx.x * 32, r0 = blockIdx.y * 32;
    const int tx = threadIdx.x & 31, ty = threadIdx.x >> 5;
#pragma unroll
    for (int j = 0; j < 4; j++)
        t[ty + j * 8][tx] = in[(size_t)(r0 + ty + j * 8) * C + c0 + tx];
    __syncthreads();
#pragma unroll
    for (int j = 0; j < 4; j++) {
        float v = t[tx][ty + j * 8];
        __half h = __float2half_rn(v);
        __half l = __float2half_rn(v - __half2float(h));
        size_t o = (size_t)(c0 + ty + j * 8) * R + r0 + tx;
        oh[o] = h;
        ol[o] = l;
    }
}

// ---------------------------------------------------------------------------
// Transpose fp16 pair: ih/il [R][C] -> oh/ol [C][R], batched via blockIdx.z
// ---------------------------------------------------------------------------
__global__ void __launch_bounds__(256) transpose_pair_kernel(
    const __half* __restrict__ ih, const __half* __restrict__ il,
    __half* __restrict__ oh, __half* __restrict__ ol,
    int R, int C, size_t sin, size_t sout)
{
    __shared__ __half th[32][33];
    __shared__ __half tl[32][33];
    ih += (size_t)blockIdx.z * sin;  il += (size_t)blockIdx.z * sin;
    oh += (size_t)blockIdx.z * sout; ol += (size_t)blockIdx.z * sout;
    const int c0 = blockIdx.x * 32, r0 = blockIdx.y * 32;
    const int tx = threadIdx.x & 31, ty = threadIdx.x >> 5;
#pragma unroll
    for (int j = 0; j < 4; j++) {
        size_t src = (size_t)(r0 + ty + j * 8) * C + c0 + tx;
        th[ty + j * 8][tx] = ih[src];
        tl[ty + j * 8][tx] = il[src];
    }
    __syncthreads();
#pragma unroll
    for (int j = 0; j < 4; j++) {
        size_t dst = (size_t)(c0 + ty + j * 8) * R + r0 + tx;
        oh[dst] = th[tx][ty + j * 8];
        ol[dst] = tl[tx][ty + j * 8];
    }
}

// ---------------------------------------------------------------------------
// Masked softmax over rows of S[B*P, Q]; writes split-fp16 alpha.
// Reference-equivalent: alpha = mask*exp(s-m)/sum_masked exp(s-m).
// ---------------------------------------------------------------------------
__global__ void __launch_bounds__(256) softmax_kernel(
    const float* __restrict__ S, const int* __restrict__ qmask,
    __half* __restrict__ ah, __half* __restrict__ al)
{
    const size_t row = blockIdx.x;
    const int b = (int)(row / PD);
    const float* s = S + row * QD;
    const int* mask = qmask + (size_t)b * QD;

    __shared__ float red[256];
    const int tid = threadIdx.x;

    float vals[8];
    int mk[8];
    float m = -INFINITY;
#pragma unroll
    for (int i = 0; i < 8; i++) {
        int qq = tid + i * 256;
        vals[i] = s[qq];
        mk[i] = mask[qq];
        if (mk[i]) m = fmaxf(m, vals[i]);
    }
    red[tid] = m;
    __syncthreads();
    for (int st = 128; st > 0; st >>= 1) {
        if (tid < st) red[tid] = fmaxf(red[tid], red[tid + st]);
        __syncthreads();
    }
    m = red[0];
    __syncthreads();

    float sum = 0.f;
#pragma unroll
    for (int i = 0; i < 8; i++) {
        float e = mk[i] ? expf(vals[i] - m) : 0.f;
        vals[i] = e;
        sum += e;
    }
    red[tid] = sum;
    __syncthreads();
    for (int st = 128; st > 0; st >>= 1) {
        if (tid < st) red[tid] += red[tid + st];
        __syncthreads();
    }
    sum = red[0];

    const float inv = (sum > 0.f) ? (1.f / sum) : 0.f;
#pragma unroll
    for (int i = 0; i < 8; i++) {
        int qq = tid + i * 256;
        float a = vals[i] * inv;
        __half h = __float2half_rn(a);
        __half l = __float2half_rn(a - __half2float(h));
        ah[row * QD + qq] = h;
        al[row * QD + qq] = l;
    }
}

// ---------------------------------------------------------------------------
extern "C" void kernel_launch(void* const* d_in, const int* in_sizes, int n_in,
                              void* d_out, int out_size)
{
    const float* passage  = (const float*)d_in[0];  // [B,P,D]
    const float* question = (const float*)d_in[1];  // [B,Q,D]
    const int*   q_mask   = (const int*)  d_in[2];  // [B,Q]
    const float* W_w      = (const float*)d_in[3];  // [D,H]
    const float* W_b      = (const float*)d_in[4];  // [H]
    const float* map_w    = (const float*)d_in[5];  // [H,H]
    const float* map_b    = (const float*)d_in[6];  // [H]
    float* out = (float*)d_out;                     // [B,P,H]

    __half *pass_h, *pass_l, *ques_h, *ques_l, *Wt_h, *Wt_l, *mT_h, *mT_l;
    __half *Wp_h, *Wp_l, *Wq_h, *Wq_l, *WqT_h, *WqT_l, *al_h, *al_l, *O_h, *O_l;
    float* S;
    cudaGetSymbolAddress((void**)&pass_h, g_pass_h);
    cudaGetSymbolAddress((void**)&pass_l, g_pass_l);
    cudaGetSymbolAddress((void**)&ques_h, g_ques_h);
    cudaGetSymbolAddress((void**)&ques_l, g_ques_l);
    cudaGetSymbolAddress((void**)&Wt_h, g_Wt_h);
    cudaGetSymbolAddress((void**)&Wt_l, g_Wt_l);
    cudaGetSymbolAddress((void**)&mT_h, g_mT_h);
    cudaGetSymbolAddress((void**)&mT_l, g_mT_l);
    cudaGetSymbolAddress((void**)&Wp_h, g_Wp_h);
    cudaGetSymbolAddress((void**)&Wp_l, g_Wp_l);
    cudaGetSymbolAddress((void**)&Wq_h, g_Wq_h);
    cudaGetSymbolAddress((void**)&Wq_l, g_Wq_l);
    cudaGetSymbolAddress((void**)&WqT_h, g_WqT_h);
    cudaGetSymbolAddress((void**)&WqT_l, g_WqT_l);
    cudaGetSymbolAddress((void**)&S, g_S);
    cudaGetSymbolAddress((void**)&al_h, g_al_h);
    cudaGetSymbolAddress((void**)&al_l, g_al_l);
    cudaGetSymbolAddress((void**)&O_h, g_O_h);
    cudaGetSymbolAddress((void**)&O_l, g_O_l);

    static bool attr_set = false;
    if (!attr_set) {
        cudaFuncSetAttribute(hgemm_kernel<true, true, false>,
                             cudaFuncAttributeMaxDynamicSharedMemorySize, GEMM_SMEM);
        cudaFuncSetAttribute(hgemm_kernel<false, false, false>,
                             cudaFuncAttributeMaxDynamicSharedMemorySize, GEMM_SMEM);
        cudaFuncSetAttribute(hgemm_kernel<true, false, false>,
                             cudaFuncAttributeMaxDynamicSharedMemorySize, GEMM_SMEM);
        cudaFuncSetAttribute(hgemm_kernel<false, true, true>,
                             cudaFuncAttributeMaxDynamicSharedMemorySize, GEMM_SMEM);
        attr_set = true;
    }

    dim3 blk(256);

    // splits + transposed/split weights
    split_kernel<<<(BP * (size_t)DD) / 1024, blk>>>(passage, pass_h, pass_l);
    split_kernel<<<((size_t)BD * QD * DD) / 1024, blk>>>(question, ques_h, ques_l);
    transpose_split_kernel<<<dim3(HD / 32, DD / 32), blk>>>(W_w, Wt_h, Wt_l, DD, HD);
    transpose_split_kernel<<<dim3(HD / 32, HD / 32), blk>>>(map_w, mT_h, mT_l, HD, HD);

    // Wp = passage @ W_w + W_b  -> split out
    hgemm_kernel<true, true, false><<<dim3(HD / 128, BP / 128, 1), blk, GEMM_SMEM>>>(
        pass_h, pass_l, Wt_h, Wt_l, W_b, nullptr, Wp_h, Wp_l, DD, HD, 0, 0, 0);

    // Wq = question @ W_w + W_b -> split out
    hgemm_kernel<true, true, false><<<dim3(HD / 128, (BD * QD) / 128, 1), blk, GEMM_SMEM>>>(
        ques_h, ques_l, Wt_h, Wt_l, W_b, nullptr, Wq_h, Wq_l, DD, HD, 0, 0, 0);

    // WqT[b] = Wq[b]^T  [H,Q]
    transpose_pair_kernel<<<dim3(HD / 32, QD / 32, BD), blk>>>(
        Wq_h, Wq_l, WqT_h, WqT_l, QD, HD, (size_t)QD * HD, (size_t)HD * QD);

    // S[b] = Wp[b] @ Wq[b]^T  -> fp32
    hgemm_kernel<false, false, false><<<dim3(QD / 128, PD / 128, BD), blk, GEMM_SMEM>>>(
        Wp_h, Wp_l, Wq_h, Wq_l, nullptr, S, nullptr, nullptr, HD, QD,
        (size_t)PD * HD, (size_t)QD * HD, (size_t)PD * QD);

    // masked softmax -> split alpha
    softmax_kernel<<<BP, blk>>>(S, q_mask, al_h, al_l);

    // O[b] = alpha[b] @ Wq[b]  -> split out
    hgemm_kernel<true, false, false><<<dim3(HD / 128, PD / 128, BD), blk, GEMM_SMEM>>>(
        al_h, al_l, WqT_h, WqT_l, nullptr, nullptr, O_h, O_l, QD, HD,
        (size_t)PD * QD, (size_t)HD * QD, (size_t)PD * HD);

    // out = relu(O @ map_w + map_b) -> fp32 d_out
    hgemm_kernel<false, true, true><<<dim3(HD / 128, BP / 128, 1), blk, GEMM_SMEM>>>(
        O_h, O_l, mT_h, mT_l, map_b, out, nullptr, nullptr, HD, HD, 0, 0, 0);
}

// round 4
// speedup vs baseline: 3.2810x; 1.4127x over previous
#include <cuda_runtime.h>
#include <cuda_fp16.h>
#include <math.h>
#include <stdint.h>

// Problem dims (fixed)
#define BD 16
#define PD 2048
#define QD 2048
#define DD 1024
#define HD 1024
#define BP (BD * PD)   // 32768
#define NQPAD 1152     // compacted question length, padded (9 * 128)

// ---------------------------------------------------------------------------
// Scratch (allocation-free: __device__ globals)
// ---------------------------------------------------------------------------
__device__ __half g_pass_h [(size_t)BP * DD];
__device__ __half g_pass_l [(size_t)BP * DD];
__device__ __half g_qc_h   [(size_t)BD * NQPAD * DD];   // compacted question
__device__ __half g_qc_l   [(size_t)BD * NQPAD * DD];
__device__ __half g_Wt_h   [(size_t)HD * DD];           // W_w^T
__device__ __half g_Wt_l   [(size_t)HD * DD];
__device__ __half g_mT_h   [(size_t)HD * HD];           // map_w^T
__device__ __half g_mT_l   [(size_t)HD * HD];
__device__ __half g_Wp_h   [(size_t)BP * HD];
__device__ __half g_Wp_l   [(size_t)BP * HD];
__device__ __half g_Wq_h   [(size_t)BD * NQPAD * HD];   // compacted Wq
__device__ __half g_Wq_l   [(size_t)BD * NQPAD * HD];
__device__ __half g_WqT_h  [(size_t)BD * HD * NQPAD];
__device__ __half g_WqT_l  [(size_t)BD * HD * NQPAD];
__device__ float  g_S      [(size_t)BP * NQPAD];        // 151 MB
__device__ __half g_al_h   [(size_t)BP * NQPAD];
__device__ __half g_al_l   [(size_t)BP * NQPAD];
__device__ __half g_O_h    [(size_t)BP * HD];
__device__ __half g_O_l    [(size_t)BP * HD];
__device__ int    g_idx    [(size_t)BD * QD];
__device__ int    g_nq     [BD];

// ---------------------------------------------------------------------------
// PTX helpers (all Ampere-era: no arch-suffix gating)
// ---------------------------------------------------------------------------
__device__ __forceinline__ uint32_t smem_u32(const void* p) {
    uint32_t a;
    asm("{ .reg .u64 t; cvta.to.shared.u64 t, %1; cvt.u32.u64 %0, t; }"
        : "=r"(a) : "l"(p));
    return a;
}

__device__ __forceinline__ void cp_async16(uint32_t dst, const void* src) {
    asm volatile("cp.async.cg.shared.global [%0], [%1], 16;"
                 :: "r"(dst), "l"(src));
}
#define CP_COMMIT() asm volatile("cp.async.commit_group;")
#define CP_WAIT2()  asm volatile("cp.async.wait_group 2;")
#define CP_WAIT0()  asm volatile("cp.async.wait_group 0;")

__device__ __forceinline__ void ldsm4(uint32_t& r0, uint32_t& r1,
                                      uint32_t& r2, uint32_t& r3, uint32_t addr) {
    asm volatile("ldmatrix.sync.aligned.m8n8.x4.shared.b16 {%0,%1,%2,%3}, [%4];"
                 : "=r"(r0), "=r"(r1), "=r"(r2), "=r"(r3) : "r"(addr));
}

__device__ __forceinline__ void mma16816(float c[4], const uint32_t a[4],
                                         uint32_t b0, uint32_t b1) {
    asm volatile(
        "mma.sync.aligned.m16n8k16.row.col.f32.f16.f16.f32 "
        "{%0,%1,%2,%3}, {%4,%5,%6,%7}, {%8,%9}, {%0,%1,%2,%3};"
        : "+f"(c[0]), "+f"(c[1]), "+f"(c[2]), "+f"(c[3])
        : "r"(a[0]), "r"(a[1]), "r"(a[2]), "r"(a[3]), "r"(b0), "r"(b1));
}

// ---------------------------------------------------------------------------
// HGEMM (3xFP16 split):  C[M,N] = A[M,K] * B[N,K]^T  (NT, both K-major fp16 pairs)
// Tile 128x128x32, 256 threads (2x4 warps of 64x32), 4-stage cp.async pipeline.
// Requires M%128==0, N%128==0, K%32==0. Batched via blockIdx.z.
// SMEM rows padded to 80B (5*16B) -> conflict-free ldmatrix without XOR.
// ---------------------------------------------------------------------------
#define TILE_B   10240          // 128 rows * 80 B
#define STAGE_B  40960          // Ah, Al, Bh, Bl
#define NSTAGE   4
#define GEMM_SMEM (STAGE_B * NSTAGE)   // 163840

__device__ __forceinline__ void stage_load(
    uint32_t sbase, const __half* Ahb, const __half* Alb,
    const __half* Bhb, const __half* Blb, int kb, int K, int tid)
{
#pragma unroll
    for (int u = 0; u < 8; u++) {
        int i = tid + u * 256;
        int t = i >> 9;                 // 0..3 : Ah, Al, Bh, Bl
        int r = (i >> 2) & 127;
        int c = i & 3;
        const __half* src =
            (t == 0 ? Ahb : t == 1 ? Alb : t == 2 ? Bhb : Blb)
            + (size_t)r * K + kb * 32 + c * 8;
        uint32_t dst = sbase + t * TILE_B + r * 80 + c * 16;
        cp_async16(dst, src);
    }
}

template <bool SPLIT_OUT, bool BIAS, bool RELU>
__global__ void __launch_bounds__(256, 1) hgemm_kernel(
    const __half* __restrict__ Ah, const __half* __restrict__ Al,
    const __half* __restrict__ Bh, const __half* __restrict__ Bl,
    const float* __restrict__ bias,
    float* __restrict__ Cf, __half* __restrict__ Ch, __half* __restrict__ Cl,
    int K, int N, size_t sA, size_t sB, size_t sC)
{
    extern __shared__ char smem[];
    const uint32_t smem_base = smem_u32(smem);

    const int tid  = threadIdx.x;
    const int lane = tid & 31;
    const int wid  = tid >> 5;
    const int wm   = wid >> 2;          // 0..1
    const int wn   = wid & 3;           // 0..3
    const int bm   = blockIdx.y * 128;
    const int bn   = blockIdx.x * 128;

    const __half* Ahb = Ah + (size_t)blockIdx.z * sA + (size_t)bm * K;
    const __half* Alb = Al + (size_t)blockIdx.z * sA + (size_t)bm * K;
    const __half* Bhb = Bh + (size_t)blockIdx.z * sB + (size_t)bn * K;
    const __half* Blb = Bl + (size_t)blockIdx.z * sB + (size_t)bn * K;

    float acc[4][4][4];
#pragma unroll
    for (int i = 0; i < 4; i++)
#pragma unroll
        for (int j = 0; j < 4; j++)
#pragma unroll
            for (int r = 0; r < 4; r++) acc[i][j][r] = 0.f;

    const int nk = K / 32;

    // prologue: stages 0..2
#pragma unroll
    for (int s = 0; s < NSTAGE - 1; s++) {
        stage_load(smem_base + s * STAGE_B, Ahb, Alb, Bhb, Blb, s, K, tid);
        CP_COMMIT();
    }

    // lane-invariant fragment offsets
    const uint32_t a_off = (uint32_t)((wm * 64 + (lane & 15)) * 80 + (lane >> 4) * 16);
    const int q = lane >> 3;
    const uint32_t b_off = (uint32_t)((wn * 32 + (q >> 1) * 8 + (lane & 7)) * 80
                                      + (q & 1) * 16);

    for (int kb = 0; kb < nk; kb++) {
        CP_WAIT2();
        __syncthreads();

        if (kb + NSTAGE - 1 < nk)
            stage_load(smem_base + ((kb + NSTAGE - 1) & (NSTAGE - 1)) * STAGE_B,
                       Ahb, Alb, Bhb, Blb, kb + NSTAGE - 1, K, tid);
        CP_COMMIT();

        const uint32_t sb = smem_base + (kb & (NSTAGE - 1)) * STAGE_B;
        const uint32_t sa_h = sb;
        const uint32_t sa_l = sb + TILE_B;
        const uint32_t sb_h = sb + 2 * TILE_B;
        const uint32_t sb_l = sb + 3 * TILE_B;

#pragma unroll
        for (int kk = 0; kk < 2; kk++) {
            uint32_t ah[4][4], alr[4][4];
#pragma unroll
            for (int i = 0; i < 4; i++) {
                ldsm4(ah[i][0], ah[i][1], ah[i][2], ah[i][3],
                      sa_h + a_off + i * 1280 + kk * 32);
                ldsm4(alr[i][0], alr[i][1], alr[i][2], alr[i][3],
                      sa_l + a_off + i * 1280 + kk * 32);
            }
            uint32_t bh[4][2], bl[4][2];
#pragma unroll
            for (int jp = 0; jp < 4; jp += 2) {
                ldsm4(bh[jp][0], bh[jp][1], bh[jp + 1][0], bh[jp + 1][1],
                      sb_h + b_off + jp * 640 + kk * 32);
                ldsm4(bl[jp][0], bl[jp][1], bl[jp + 1][0], bl[jp + 1][1],
                      sb_l + b_off + jp * 640 + kk * 32);
            }
#pragma unroll
            for (int i = 0; i < 4; i++)
#pragma unroll
                for (int j = 0; j < 4; j++) {
                    mma16816(acc[i][j], ah[i],  bh[j][0], bh[j][1]);
                    mma16816(acc[i][j], ah[i],  bl[j][0], bl[j][1]);
                    mma16816(acc[i][j], alr[i], bh[j][0], bh[j][1]);
                }
        }
    }

    // ---- epilogue
    CP_WAIT0();
#pragma unroll
    for (int i = 0; i < 4; i++) {
        const int row0 = bm + wm * 64 + i * 16 + (lane >> 2);
        const size_t b0 = (size_t)blockIdx.z * sC + (size_t)row0 * N;
        const size_t b1 = b0 + (size_t)8 * N;
#pragma unroll
        for (int j = 0; j < 4; j++) {
            const int col = bn + wn * 32 + j * 8 + 2 * (lane & 3);
            float c0 = acc[i][j][0], c1 = acc[i][j][1];
            float c2 = acc[i][j][2], c3 = acc[i][j][3];
            if (BIAS) {
                const float bb0 = bias[col], bb1 = bias[col + 1];
                c0 += bb0; c1 += bb1; c2 += bb0; c3 += bb1;
            }
            if (RELU) {
                c0 = fmaxf(c0, 0.f); c1 = fmaxf(c1, 0.f);
                c2 = fmaxf(c2, 0.f); c3 = fmaxf(c3, 0.f);
            }
            if (SPLIT_OUT) {
                __half h0 = __float2half_rn(c0), h1 = __float2half_rn(c1);
                __half h2 = __float2half_rn(c2), h3 = __float2half_rn(c3);
                __half l0 = __float2half_rn(c0 - __half2float(h0));
                __half l1 = __float2half_rn(c1 - __half2float(h1));
                __half l2 = __float2half_rn(c2 - __half2float(h2));
                __half l3 = __float2half_rn(c3 - __half2float(h3));
                *(__half2*)(Ch + b0 + col) = __halves2half2(h0, h1);
                *(__half2*)(Ch + b1 + col) = __halves2half2(h2, h3);
                *(__half2*)(Cl + b0 + col) = __halves2half2(l0, l1);
                *(__half2*)(Cl + b1 + col) = __halves2half2(l2, l3);
            } else {
                *(float2*)(Cf + b0 + col) = make_float2(c0, c1);
                *(float2*)(Cf + b1 + col) = make_float2(c2, c3);
            }
        }
    }
}

// ---------------------------------------------------------------------------
// Elementwise fp32 -> (hi, lo) fp16 split.
// ---------------------------------------------------------------------------
__global__ void __launch_bounds__(256) split_kernel(
    const float* __restrict__ in, __half* __restrict__ oh,
    __half* __restrict__ ol)
{
    const size_t idx = (size_t)blockIdx.x * 256 + threadIdx.x;
    float4 v = ((const float4*)in)[idx];
    __half h0 = __float2half_rn(v.x), h1 = __float2half_rn(v.y);
    __half h2 = __float2half_rn(v.z), h3 = __float2half_rn(v.w);
    __half l0 = __float2half_rn(v.x - __half2float(h0));
    __half l1 = __float2half_rn(v.y - __half2float(h1));
    __half l2 = __float2half_rn(v.z - __half2float(h2));
    __half l3 = __float2half_rn(v.w - __half2float(h3));
    ((__half2*)oh)[idx * 2]     = __halves2half2(h0, h1);
    ((__half2*)oh)[idx * 2 + 1] = __halves2half2(h2, h3);
    ((__half2*)ol)[idx * 2]     = __halves2half2(l0, l1);
    ((__half2*)ol)[idx * 2 + 1] = __halves2half2(l2, l3);
}

// ---------------------------------------------------------------------------
// Transpose + split: fp32 in[R][C] -> oh/ol [C][R] fp16
// ---------------------------------------------------------------------------
__global__ void __launch_bounds__(256) transpose_split_kernel(
    const float* __restrict__ in, __half* __restrict__ oh,
    __half* __restrict__ ol, int R, int C)
{
    __shared__ float t[32][33];
    const int c0 = blockIdx.x * 32, r0 = blockIdx.y * 32;
    const int tx = threadIdx.x & 31, ty = threadIdx.x >> 5;
#pragma unroll
    for (int j = 0; j < 4; j++)
        t[ty + j * 8][tx] = in[(size_t)(r0 + ty + j * 8) * C + c0 + tx];
    __syncthreads();
#pragma unroll
    for (int j = 0; j < 4; j++) {
        float v = t[tx][ty + j * 8];
        __half h = __float2half_rn(v);
        __half l = __float2half_rn(v - __half2float(h));
        size_t o = (size_t)(c0 + ty + j * 8) * R + r0 + tx;
        oh[o] = h;
        ol[o] = l;
    }
}

// ---------------------------------------------------------------------------
// Transpose fp16 pair: ih/il [R][C] -> oh/ol [C][R], batched via blockIdx.z
// ---------------------------------------------------------------------------
__global__ void __launch_bounds__(256) transpose_pair_kernel(
    const __half* __restrict__ ih, const __half* __restrict__ il,
    __half* __restrict__ oh, __half* __restrict__ ol,
    int R, int C, size_t sin, size_t sout)
{
    __shared__ __half th[32][33];
    __shared__ __half tl[32][33];
    ih += (size_t)blockIdx.z * sin;  il += (size_t)blockIdx.z * sin;
    oh += (size_t)blockIdx.z * sout; ol += (size_t)blockIdx.z * sout;
    const int c0 = blockIdx.x * 32, r0 = blockIdx.y * 32;
    const int tx = threadIdx.x & 31, ty = threadIdx.x >> 5;
#pragma unroll
    for (int j = 0; j < 4; j++) {
        size_t src = (size_t)(r0 + ty + j * 8) * C + c0 + tx;
        th[ty + j * 8][tx] = ih[src];
        tl[ty + j * 8][tx] = il[src];
    }
    __syncthreads();
#pragma unroll
    for (int j = 0; j < 4; j++) {
        size_t dst = (size_t)(c0 + ty + j * 8) * R + r0 + tx;
        oh[dst] = th[tx][ty + j * 8];
        ol[dst] = tl[tx][ty + j * 8];
    }
}

// ---------------------------------------------------------------------------
// Per-batch deterministic mask scan: active q indices + count.
// One block of 256 per batch; each thread scans 8 elements.
// ---------------------------------------------------------------------------
__global__ void __launch_bounds__(256) mask_scan_kernel(
    const int* __restrict__ qmask, int* __restrict__ idx, int* __restrict__ nq)
{
    const int b = blockIdx.x;
    const int* m = qmask + (size_t)b * QD;
    __shared__ int cnt[256];
    const int tid = threadIdx.x;

    int loc[8];
    int c = 0;
#pragma unroll
    for (int j = 0; j < 8; j++) {
        loc[j] = m[tid * 8 + j];
        c += loc[j];
    }
    cnt[tid] = c;
    __syncthreads();
    // Hillis-Steele inclusive scan
    for (int off = 1; off < 256; off <<= 1) {
        int v = (tid >= off) ? cnt[tid - off] : 0;
        __syncthreads();
        cnt[tid] += v;
        __syncthreads();
    }
    int base = cnt[tid] - c;   // exclusive
#pragma unroll
    for (int j = 0; j < 8; j++) {
        if (loc[j]) {
            if (base < NQPAD) idx[(size_t)b * QD + base] = tid * 8 + j;
            base++;
        }
    }
    if (tid == 255) nq[b] = cnt[255] < NQPAD ? cnt[255] : NQPAD;
}

// ---------------------------------------------------------------------------
// Gather active question rows + split to fp16 pair; pad rows -> zeros.
// Grid: B*NQPAD blocks of 256 (one row each; D=1024 -> one float4/thread).
// ---------------------------------------------------------------------------
__global__ void __launch_bounds__(256) gather_split_kernel(
    const float* __restrict__ question, const int* __restrict__ idx,
    const int* __restrict__ nq, __half* __restrict__ oh, __half* __restrict__ ol)
{
    const int r = blockIdx.x % NQPAD;
    const int b = blockIdx.x / NQPAD;
    const int tid = threadIdx.x;
    const size_t dst = ((size_t)b * NQPAD + r) * DD + tid * 4;

    if (r < nq[b]) {
        const int src_row = idx[(size_t)b * QD + r];
        float4 v = *(const float4*)(question + ((size_t)b * QD + src_row) * DD + tid * 4);
        __half h0 = __float2half_rn(v.x), h1 = __float2half_rn(v.y);
        __half h2 = __float2half_rn(v.z), h3 = __float2half_rn(v.w);
        __half l0 = __float2half_rn(v.x - __half2float(h0));
        __half l1 = __float2half_rn(v.y - __half2float(h1));
        __half l2 = __float2half_rn(v.z - __half2float(h2));
        __half l3 = __float2half_rn(v.w - __half2float(h3));
        *(__half2*)(oh + dst)     = __halves2half2(h0, h1);
        *(__half2*)(oh + dst + 2) = __halves2half2(h2, h3);
        *(__half2*)(ol + dst)     = __halves2half2(l0, l1);
        *(__half2*)(ol + dst + 2) = __halves2half2(l2, l3);
    } else {
        *(float2*)(oh + dst) = make_float2(0.f, 0.f);   // 4 halves = 0
        *(float2*)(ol + dst) = make_float2(0.f, 0.f);
    }
}

// ---------------------------------------------------------------------------
// Softmax over compacted rows S[BP, NQPAD], active cols = nq[b].
// Writes split-fp16 alpha with zeros in pad columns.
// ---------------------------------------------------------------------------
#define SMX_IT ((NQPAD + 255) / 256)   // 5
__global__ void __launch_bounds__(256) softmax_kernel(
    const float* __restrict__ S, const int* __restrict__ nq_arr,
    __half* __restrict__ ah, __half* __restrict__ al)
{
    const size_t row = blockIdx.x;
    const int b = (int)(row / PD);
    const float* s = S + row * NQPAD;
    const int nq = nq_arr[b];

    __shared__ float red[256];
    const int tid = threadIdx.x;

    float vals[SMX_IT];
    float m = -INFINITY;
#pragma unroll
    for (int i = 0; i < SMX_IT; i++) {
        int qq = tid + i * 256;
        vals[i] = (qq < NQPAD) ? s[qq] : 0.f;
        if (qq < nq) m = fmaxf(m, vals[i]);
    }
    red[tid] = m;
    __syncthreads();
    for (int st = 128; st > 0; st >>= 1) {
        if (tid < st) red[tid] = fmaxf(red[tid], red[tid + st]);
        __syncthreads();
    }
    m = red[0];
    __syncthreads();

    float sum = 0.f;
#pragma unroll
    for (int i = 0; i < SMX_IT; i++) {
        int qq = tid + i * 256;
        float e = (qq < nq) ? expf(vals[i] - m) : 0.f;
        vals[i] = e;
        sum += e;
    }
    red[tid] = sum;
    __syncthreads();
    for (int st = 128; st > 0; st >>= 1) {
        if (tid < st) red[tid] += red[tid + st];
        __syncthreads();
    }
    sum = red[0];

    const float inv = (sum > 0.f) ? (1.f / sum) : 0.f;
#pragma unroll
    for (int i = 0; i < SMX_IT; i++) {
        int qq = tid + i * 256;
        if (qq < NQPAD) {
            float a = vals[i] * inv;
            __half h = __float2half_rn(a);
            __half l = __float2half_rn(a - __half2float(h));
            ah[row * NQPAD + qq] = h;
            al[row * NQPAD + qq] = l;
        }
    }
}

// ---------------------------------------------------------------------------
extern "C" void kernel_launch(void* const* d_in, const int* in_sizes, int n_in,
                              void* d_out, int out_size)
{
    const float* passage  = (const float*)d_in[0];  // [B,P,D]
    const float* question = (const float*)d_in[1];  // [B,Q,D]
    const int*   q_mask   = (const int*)  d_in[2];  // [B,Q]
    const float* W_w      = (const float*)d_in[3];  // [D,H]
    const float* W_b      = (const float*)d_in[4];  // [H]
    const float* map_w    = (const float*)d_in[5];  // [H,H]
    const float* map_b    = (const float*)d_in[6];  // [H]
    float* out = (float*)d_out;                     // [B,P,H]

    __half *pass_h, *pass_l, *qc_h, *qc_l, *Wt_h, *Wt_l, *mT_h, *mT_l;
    __half *Wp_h, *Wp_l, *Wq_h, *Wq_l, *WqT_h, *WqT_l, *al_h, *al_l, *O_h, *O_l;
    float* S;
    int *idx, *nq;
    cudaGetSymbolAddress((void**)&pass_h, g_pass_h);
    cudaGetSymbolAddress((void**)&pass_l, g_pass_l);
    cudaGetSymbolAddress((void**)&qc_h, g_qc_h);
    cudaGetSymbolAddress((void**)&qc_l, g_qc_l);
    cudaGetSymbolAddress((void**)&Wt_h, g_Wt_h);
    cudaGetSymbolAddress((void**)&Wt_l, g_Wt_l);
    cudaGetSymbolAddress((void**)&mT_h, g_mT_h);
    cudaGetSymbolAddress((void**)&mT_l, g_mT_l);
    cudaGetSymbolAddress((void**)&Wp_h, g_Wp_h);
    cudaGetSymbolAddress((void**)&Wp_l, g_Wp_l);
    cudaGetSymbolAddress((void**)&Wq_h, g_Wq_h);
    cudaGetSymbolAddress((void**)&Wq_l, g_Wq_l);
    cudaGetSymbolAddress((void**)&WqT_h, g_WqT_h);
    cudaGetSymbolAddress((void**)&WqT_l, g_WqT_l);
    cudaGetSymbolAddress((void**)&S, g_S);
    cudaGetSymbolAddress((void**)&al_h, g_al_h);
    cudaGetSymbolAddress((void**)&al_l, g_al_l);
    cudaGetSymbolAddress((void**)&O_h, g_O_h);
    cudaGetSymbolAddress((void**)&O_l, g_O_l);
    cudaGetSymbolAddress((void**)&idx, g_idx);
    cudaGetSymbolAddress((void**)&nq, g_nq);

    static bool attr_set = false;
    if (!attr_set) {
        cudaFuncSetAttribute(hgemm_kernel<true, true, false>,
                             cudaFuncAttributeMaxDynamicSharedMemorySize, GEMM_SMEM);
        cudaFuncSetAttribute(hgemm_kernel<false, false, false>,
                             cudaFuncAttributeMaxDynamicSharedMemorySize, GEMM_SMEM);
        cudaFuncSetAttribute(hgemm_kernel<true, false, false>,
                             cudaFuncAttributeMaxDynamicSharedMemorySize, GEMM_SMEM);
        cudaFuncSetAttribute(hgemm_kernel<false, true, true>,
                             cudaFuncAttributeMaxDynamicSharedMemorySize, GEMM_SMEM);
        attr_set = true;
    }

    dim3 blk(256);

    // mask scan + compact gather of question
    mask_scan_kernel<<<BD, blk>>>(q_mask, idx, nq);
    gather_split_kernel<<<BD * NQPAD, blk>>>(question, idx, nq, qc_h, qc_l);

    // splits + transposed/split weights
    split_kernel<<<(BP * (size_t)DD) / 1024, blk>>>(passage, pass_h, pass_l);
    transpose_split_kernel<<<dim3(HD / 32, DD / 32), blk>>>(W_w, Wt_h, Wt_l, DD, HD);
    transpose_split_kernel<<<dim3(HD / 32, HD / 32), blk>>>(map_w, mT_h, mT_l, HD, HD);

    // Wp = passage @ W_w + W_b  -> split out  [BP, H]
    hgemm_kernel<true, true, false><<<dim3(HD / 128, BP / 128, 1), blk, GEMM_SMEM>>>(
        pass_h, pass_l, Wt_h, Wt_l, W_b, nullptr, Wp_h, Wp_l, DD, HD, 0, 0, 0);

    // Wq' = qc @ W_w + W_b -> split out  [B*NQPAD, H]  (pad rows = bias, harmless)
    hgemm_kernel<true, true, false><<<dim3(HD / 128, (BD * NQPAD) / 128, 1), blk, GEMM_SMEM>>>(
        qc_h, qc_l, Wt_h, Wt_l, W_b, nullptr, Wq_h, Wq_l, DD, HD, 0, 0, 0);

    // WqT'[b] = Wq'[b]^T  [H, NQPAD]
    transpose_pair_kernel<<<dim3(HD / 32, NQPAD / 32, BD), blk>>>(
        Wq_h, Wq_l, WqT_h, WqT_l, NQPAD, HD, (size_t)NQPAD * HD, (size_t)HD * NQPAD);

    // S'[b] = Wp[b] @ Wq'[b]^T  -> fp32  [P, NQPAD]
    hgemm_kernel<false, false, false><<<dim3(NQPAD / 128, PD / 128, BD), blk, GEMM_SMEM>>>(
        Wp_h, Wp_l, Wq_h, Wq_l, nullptr, S, nullptr, nullptr, HD, NQPAD,
        (size_t)PD * HD, (size_t)NQPAD * HD, (size_t)PD * NQPAD);

    // softmax over active cols -> split alpha (pad cols zero)
    softmax_kernel<<<BP, blk>>>(S, nq, al_h, al_l);

    // O[b] = alpha'[b] @ Wq'[b]  -> split out  [P, H]
    hgemm_kernel<true, false, false><<<dim3(HD / 128, PD / 128, BD), blk, GEMM_SMEM>>>(
        al_h, al_l, WqT_h, WqT_l, nullptr, nullptr, O_h, O_l, NQPAD, HD,
        (size_t)PD * NQPAD, (size_t)HD * NQPAD, (size_t)PD * HD);

    // out = relu(O @ map_w + map_b) -> fp32 d_out
    hgemm_kernel<false, true, true><<<dim3(HD / 128, BP / 128, 1), blk, GEMM_SMEM>>>(
        O_h, O_l, mT_h, mT_l, map_b, out, nullptr, nullptr, HD, HD, 0, 0, 0);
}

// round 6
// speedup vs baseline: 3.6663x; 1.1174x over previous
#include <cuda_runtime.h>
#include <cuda_fp16.h>
#include <math.h>
#include <stdint.h>

// Problem dims (fixed)
#define BD 16
#define PD 2048
#define QD 2048
#define DD 1024
#define HD 1024
#define BP (BD * PD)   // 32768
#define NQPAD 1152     // compacted question length, padded (9 * 128)

// ---------------------------------------------------------------------------
// Scratch (allocation-free: __device__ globals)
// ---------------------------------------------------------------------------
__device__ __half g_pass_h [(size_t)BP * DD];
__device__ __half g_pass_l [(size_t)BP * DD];
__device__ __half g_qc_h   [(size_t)BD * NQPAD * DD];   // compacted question
__device__ __half g_qc_l   [(size_t)BD * NQPAD * DD];
__device__ __half g_Wt_h   [(size_t)HD * DD];           // W_w^T
__device__ __half g_Wt_l   [(size_t)HD * DD];
__device__ __half g_mT_h   [(size_t)HD * HD];           // map_w^T
__device__ __half g_mT_l   [(size_t)HD * HD];
__device__ __half g_Wp_h   [(size_t)BP * HD];
__device__ __half g_Wp_l   [(size_t)BP * HD];
__device__ __half g_Wq_h   [(size_t)BD * NQPAD * HD];   // compacted Wq
__device__ __half g_Wq_l   [(size_t)BD * NQPAD * HD];
__device__ __half g_WqT_h  [(size_t)BD * HD * NQPAD];
__device__ __half g_WqT_l  [(size_t)BD * HD * NQPAD];
__device__ float  g_S      [(size_t)BP * NQPAD];        // 151 MB
__device__ __half g_al_h   [(size_t)BP * NQPAD];
__device__ __half g_al_l   [(size_t)BP * NQPAD];
__device__ __half g_O_h    [(size_t)BP * HD];
__device__ __half g_O_l    [(size_t)BP * HD];
__device__ int    g_idx    [(size_t)BD * QD];
__device__ int    g_nq     [BD];

// ---------------------------------------------------------------------------
// PTX helpers (all Ampere-era: no arch-suffix gating)
// ---------------------------------------------------------------------------
__device__ __forceinline__ uint32_t smem_u32(const void* p) {
    uint32_t a;
    asm("{ .reg .u64 t; cvta.to.shared.u64 t, %1; cvt.u32.u64 %0, t; }"
        : "=r"(a) : "l"(p));
    return a;
}

__device__ __forceinline__ void cp_async16(uint32_t dst, const void* src) {
    asm volatile("cp.async.cg.shared.global [%0], [%1], 16;"
                 :: "r"(dst), "l"(src));
}
#define CP_COMMIT() asm volatile("cp.async.commit_group;")
#define CP_WAIT1()  asm volatile("cp.async.wait_group 1;")

__device__ __forceinline__ void ldsm4(uint32_t& r0, uint32_t& r1,
                                      uint32_t& r2, uint32_t& r3, uint32_t addr) {
    asm volatile("ldmatrix.sync.aligned.m8n8.x4.shared.b16 {%0,%1,%2,%3}, [%4];"
                 : "=r"(r0), "=r"(r1), "=r"(r2), "=r"(r3) : "r"(addr));
}

__device__ __forceinline__ void mma16816(float c[4], const uint32_t a[4],
                                         uint32_t b0, uint32_t b1) {
    asm volatile(
        "mma.sync.aligned.m16n8k16.row.col.f32.f16.f16.f32 "
        "{%0,%1,%2,%3}, {%4,%5,%6,%7}, {%8,%9}, {%0,%1,%2,%3};"
        : "+f"(c[0]), "+f"(c[1]), "+f"(c[2]), "+f"(c[3])
        : "r"(a[0]), "r"(a[1]), "r"(a[2]), "r"(a[3]), "r"(b0), "r"(b1));
}

// ---------------------------------------------------------------------------
// HGEMM (3xFP16 split): C[M,N] = A[M,K] * B[N,K]^T (NT, both K-major fp16 pairs)
// Block BM x BN (BM*BN = 32768), 256 threads, warp tile 64x64, K-block 32,
// 3-stage cp.async pipeline. Requires M%BM==0, N%BN==0, K%32==0.
// SMEM rows padded to 80B (5*16B) -> conflict-free ldmatrix without XOR.
// ---------------------------------------------------------------------------
#define NSTAGE   3
#define STAGE_B  61440          // (BM+BN)*160 with BM+BN=384
#define GEMM_SMEM (STAGE_B * NSTAGE)   // 184320

template <int BM, int BN>
__device__ __forceinline__ void stage_load(
    uint32_t sbase, const __half* Ahb, const __half* Alb,
    const __half* Bhb, const __half* Blb, int kb, int K, int tid)
{
    // chunk layout: [0,BM*4) Ah | [BM*4,BM*8) Al | [.., +BN*4) Bh | [.., +BN*4) Bl
#pragma unroll
    for (int u = 0; u < 12; u++) {
        int i = tid + u * 256;
        const __half* src;
        uint32_t dst;
        if (i < BM * 4) {
            int r = i >> 2, c = i & 3;
            src = Ahb + (size_t)r * K + kb * 32 + c * 8;
            dst = sbase + r * 80 + c * 16;
        } else if (i < BM * 8) {
            int j = i - BM * 4; int r = j >> 2, c = j & 3;
            src = Alb + (size_t)r * K + kb * 32 + c * 8;
            dst = sbase + BM * 80 + r * 80 + c * 16;
        } else if (i < BM * 8 + BN * 4) {
            int j = i - BM * 8; int r = j >> 2, c = j & 3;
            src = Bhb + (size_t)r * K + kb * 32 + c * 8;
            dst = sbase + 2 * BM * 80 + r * 80 + c * 16;
        } else {
            int j = i - BM * 8 - BN * 4; int r = j >> 2, c = j & 3;
            src = Blb + (size_t)r * K + kb * 32 + c * 8;
            dst = sbase + 2 * BM * 80 + BN * 80 + r * 80 + c * 16;
        }
        cp_async16(dst, src);
    }
}

template <int BM, int BN, bool SPLIT_OUT, bool BIAS, bool RELU>
__global__ void __launch_bounds__(256, 1) hgemm_kernel(
    const __half* __restrict__ Ah, const __half* __restrict__ Al,
    const __half* __restrict__ Bh, const __half* __restrict__ Bl,
    const float* __restrict__ bias,
    float* __restrict__ Cf, __half* __restrict__ Ch, __half* __restrict__ Cl,
    int K, int N, size_t sA, size_t sB, size_t sC)
{
    extern __shared__ char smem[];
    const uint32_t smem_base = smem_u32(smem);

    constexpr int WN = BN / 64;         // warps along N
    const int tid  = threadIdx.x;
    const int lane = tid & 31;
    const int wid  = tid >> 5;
    const int wm   = wid / WN;
    const int wn   = wid % WN;
    const int bm   = blockIdx.y * BM;
    const int bn   = blockIdx.x * BN;

    const __half* Ahb = Ah + (size_t)blockIdx.z * sA + (size_t)bm * K;
    const __half* Alb = Al + (size_t)blockIdx.z * sA + (size_t)bm * K;
    const __half* Bhb = Bh + (size_t)blockIdx.z * sB + (size_t)bn * K;
    const __half* Blb = Bl + (size_t)blockIdx.z * sB + (size_t)bn * K;

    float acc[4][8][4];
#pragma unroll
    for (int i = 0; i < 4; i++)
#pragma unroll
        for (int j = 0; j < 8; j++)
#pragma unroll
            for (int r = 0; r < 4; r++) acc[i][j][r] = 0.f;

    const int nk = K / 32;

    // prologue: stages 0,1
#pragma unroll
    for (int s = 0; s < NSTAGE - 1; s++) {
        stage_load<BM, BN>(smem_base + s * STAGE_B, Ahb, Alb, Bhb, Blb, s, K, tid);
        CP_COMMIT();
    }

    // lane-invariant fragment offsets
    const uint32_t a_off = (uint32_t)((wm * 64 + (lane & 15)) * 80 + (lane >> 4) * 16);
    const int q = lane >> 3;
    const uint32_t b_off = (uint32_t)((wn * 64 + (q >> 1) * 8 + (lane & 7)) * 80
                                      + (q & 1) * 16);

    int sidx = 0;   // stage index = kb % 3
    for (int kb = 0; kb < nk; kb++) {
        CP_WAIT1();
        __syncthreads();

        if (kb + NSTAGE - 1 < nk) {
            int ls = sidx + (NSTAGE - 1); if (ls >= NSTAGE) ls -= NSTAGE;
            stage_load<BM, BN>(smem_base + ls * STAGE_B,
                               Ahb, Alb, Bhb, Blb, kb + NSTAGE - 1, K, tid);
        }
        CP_COMMIT();

        const uint32_t sb = smem_base + sidx * STAGE_B;
        const uint32_t sa_h = sb;
        const uint32_t sa_l = sb + BM * 80;
        const uint32_t sb_h = sb + 2 * BM * 80;
        const uint32_t sb_l = sb + 2 * BM * 80 + BN * 80;

#pragma unroll
        for (int kk = 0; kk < 2; kk++) {
            uint32_t ah[4][4], alr[4][4];
#pragma unroll
            for (int i = 0; i < 4; i++) {
                ldsm4(ah[i][0], ah[i][1], ah[i][2], ah[i][3],
                      sa_h + a_off + i * 1280 + kk * 32);
                ldsm4(alr[i][0], alr[i][1], alr[i][2], alr[i][3],
                      sa_l + a_off + i * 1280 + kk * 32);
            }
            uint32_t bh[8][2], bl[8][2];
#pragma unroll
            for (int jp = 0; jp < 8; jp += 2) {
                ldsm4(bh[jp][0], bh[jp][1], bh[jp + 1][0], bh[jp + 1][1],
                      sb_h + b_off + jp * 640 + kk * 32);
                ldsm4(bl[jp][0], bl[jp][1], bl[jp + 1][0], bl[jp + 1][1],
                      sb_l + b_off + jp * 640 + kk * 32);
            }
#pragma unroll
            for (int i = 0; i < 4; i++)
#pragma unroll
                for (int j = 0; j < 8; j++) {
                    mma16816(acc[i][j], ah[i],  bh[j][0], bh[j][1]);
                    mma16816(acc[i][j], ah[i],  bl[j][0], bl[j][1]);
                    mma16816(acc[i][j], alr[i], bh[j][0], bh[j][1]);
                }
        }
        if (++sidx >= NSTAGE) sidx = 0;
    }

    // ---- epilogue
#pragma unroll
    for (int i = 0; i < 4; i++) {
        const int row0 = bm + wm * 64 + i * 16 + (lane >> 2);
        const size_t b0 = (size_t)blockIdx.z * sC + (size_t)row0 * N;
        const size_t b1 = b0 + (size_t)8 * N;
#pragma unroll
        for (int j = 0; j < 8; j++) {
            const int col = bn + wn * 64 + j * 8 + 2 * (lane & 3);
            float c0 = acc[i][j][0], c1 = acc[i][j][1];
            float c2 = acc[i][j][2], c3 = acc[i][j][3];
            if (BIAS) {
                const float bb0 = bias[col], bb1 = bias[col + 1];
                c0 += bb0; c1 += bb1; c2 += bb0; c3 += bb1;
            }
            if (RELU) {
                c0 = fmaxf(c0, 0.f); c1 = fmaxf(c1, 0.f);
                c2 = fmaxf(c2, 0.f); c3 = fmaxf(c3, 0.f);
            }
            if (SPLIT_OUT) {
                __half h0 = __float2half_rn(c0), h1 = __float2half_rn(c1);
                __half h2 = __float2half_rn(c2), h3 = __float2half_rn(c3);
                __half l0 = __float2half_rn(c0 - __half2float(h0));
                __half l1 = __float2half_rn(c1 - __half2float(h1));
                __half l2 = __float2half_rn(c2 - __half2float(h2));
                __half l3 = __float2half_rn(c3 - __half2float(h3));
                *(__half2*)(Ch + b0 + col) = __halves2half2(h0, h1);
                *(__half2*)(Ch + b1 + col) = __halves2half2(h2, h3);
                *(__half2*)(Cl + b0 + col) = __halves2half2(l0, l1);
                *(__half2*)(Cl + b1 + col) = __halves2half2(l2, l3);
            } else {
                *(float2*)(Cf + b0 + col) = make_float2(c0, c1);
                *(float2*)(Cf + b1 + col) = make_float2(c2, c3);
            }
        }
    }
}

// ---------------------------------------------------------------------------
// Elementwise fp32 -> (hi, lo) fp16 split.
// ---------------------------------------------------------------------------
__global__ void __launch_bounds__(256) split_kernel(
    const float* __restrict__ in, __half* __restrict__ oh,
    __half* __restrict__ ol)
{
    const size_t idx = (size_t)blockIdx.x * 256 + threadIdx.x;
    float4 v = ((const float4*)in)[idx];
    __half h0 = __float2half_rn(v.x), h1 = __float2half_rn(v.y);
    __half h2 = __float2half_rn(v.z), h3 = __float2half_rn(v.w);
    __half l0 = __float2half_rn(v.x - __half2float(h0));
    __half l1 = __float2half_rn(v.y - __half2float(h1));
    __half l2 = __float2half_rn(v.z - __half2float(h2));
    __half l3 = __float2half_rn(v.w - __half2float(h3));
    ((__half2*)oh)[idx * 2]     = __halves2half2(h0, h1);
    ((__half2*)oh)[idx * 2 + 1] = __halves2half2(h2, h3);
    ((__half2*)ol)[idx * 2]     = __halves2half2(l0, l1);
    ((__half2*)ol)[idx * 2 + 1] = __halves2half2(l2, l3);
}

// ---------------------------------------------------------------------------
// Transpose + split: fp32 in[R][C] -> oh/ol [C][R] fp16
// ---------------------------------------------------------------------------
__global__ void __launch_bounds__(256) transpose_split_kernel(
    const float* __restrict__ in, __half* __restrict__ oh,
    __half* __restrict__ ol, int R, int C)
{
    __shared__ float t[32][33];
    const int c0 = blockIdx.x * 32, r0 = blockIdx.y * 32;
    const int tx = threadIdx.x & 31, ty = threadIdx.x >> 5;
#pragma unroll
    for (int j = 0; j < 4; j++)
        t[ty + j * 8][tx] = in[(size_t)(r0 + ty + j * 8) * C + c0 + tx];
    __syncthreads();
#pragma unroll
    for (int j = 0; j < 4; j++) {
        float v = t[tx][ty + j * 8];
        __half h = __float2half_rn(v);
        __half l = __float2half_rn(v - __half2float(h));
        size_t o = (size_t)(c0 + ty + j * 8) * R + r0 + tx;
        oh[o] = h;
        ol[o] = l;
    }
}

// ---------------------------------------------------------------------------
// Transpose fp16 pair: ih/il [R][C] -> oh/ol [C][R], batched via blockIdx.z
// ---------------------------------------------------------------------------
__global__ void __launch_bounds__(256) transpose_pair_kernel(
    const __half* __restrict__ ih, const __half* __restrict__ il,
    __half* __restrict__ oh, __half* __restrict__ ol,
    int R, int C, size_t sin, size_t sout)
{
    __shared__ __half th[32][33];
    __shared__ __half tl[32][33];
    ih += (size_t)blockIdx.z * sin;  il += (size_t)blockIdx.z * sin;
    oh += (size_t)blockIdx.z * sout; ol += (size_t)blockIdx.z * sout;
    const int c0 = blockIdx.x * 32, r0 = blockIdx.y * 32;
    const int tx = threadIdx.x & 31, ty = threadIdx.x >> 5;
#pragma unroll
    for (int j = 0; j < 4; j++) {
        size_t src = (size_t)(r0 + ty + j * 8) * C + c0 + tx;
        th[ty + j * 8][tx] = ih[src];
        tl[ty + j * 8][tx] = il[src];
    }
    __syncthreads();
#pragma unroll
    for (int j = 0; j < 4; j++) {
        size_t dst = (size_t)(c0 + ty + j * 8) * R + r0 + tx;
        oh[dst] = th[tx][ty + j * 8];
        ol[dst] = tl[tx][ty + j * 8];
    }
}

// ---------------------------------------------------------------------------
// Per-batch deterministic mask scan: active q indices + count.
// ---------------------------------------------------------------------------
__global__ void __launch_bounds__(256) mask_scan_kernel(
    const int* __restrict__ qmask, int* __restrict__ idx, int* __restrict__ nq)
{
    const int b = blockIdx.x;
    const int* m = qmask + (size_t)b * QD;
    __shared__ int cnt[256];
    const int tid = threadIdx.x;

    int loc[8];
    int c = 0;
#pragma unroll
    for (int j = 0; j < 8; j++) {
        loc[j] = m[tid * 8 + j];
        c += loc[j];
    }
    cnt[tid] = c;
    __syncthreads();
    for (int off = 1; off < 256; off <<= 1) {
        int v = (tid >= off) ? cnt[tid - off] : 0;
        __syncthreads();
        cnt[tid] += v;
        __syncthreads();
    }
    int base = cnt[tid] - c;   // exclusive
#pragma unroll
    for (int j = 0; j < 8; j++) {
        if (loc[j]) {
            if (base < NQPAD) idx[(size_t)b * QD + base] = tid * 8 + j;
            base++;
        }
    }
    if (tid == 255) nq[b] = cnt[255] < NQPAD ? cnt[255] : NQPAD;
}

// ---------------------------------------------------------------------------
// Gather active question rows + split to fp16 pair; pad rows -> zeros.
// ---------------------------------------------------------------------------
__global__ void __launch_bounds__(256) gather_split_kernel(
    const float* __restrict__ question, const int* __restrict__ idx,
    const int* __restrict__ nq, __half* __restrict__ oh, __half* __restrict__ ol)
{
    const int r = blockIdx.x % NQPAD;
    const int b = blockIdx.x / NQPAD;
    const int tid = threadIdx.x;
    const size_t dst = ((size_t)b * NQPAD + r) * DD + tid * 4;

    if (r < nq[b]) {
        const int src_row = idx[(size_t)b * QD + r];
        float4 v = *(const float4*)(question + ((size_t)b * QD + src_row) * DD + tid * 4);
        __half h0 = __float2half_rn(v.x), h1 = __float2half_rn(v.y);
        __half h2 = __float2half_rn(v.z), h3 = __float2half_rn(v.w);
        __half l0 = __float2half_rn(v.x - __half2float(h0));
        __half l1 = __float2half_rn(v.y - __half2float(h1));
        __half l2 = __float2half_rn(v.z - __half2float(h2));
        __half l3 = __float2half_rn(v.w - __half2float(h3));
        *(__half2*)(oh + dst)     = __halves2half2(h0, h1);
        *(__half2*)(oh + dst + 2) = __halves2half2(h2, h3);
        *(__half2*)(ol + dst)     = __halves2half2(l0, l1);
        *(__half2*)(ol + dst + 2) = __halves2half2(l2, l3);
    } else {
        *(float2*)(oh + dst) = make_float2(0.f, 0.f);
        *(float2*)(ol + dst) = make_float2(0.f, 0.f);
    }
}

// ---------------------------------------------------------------------------
// Softmax over compacted rows S[BP, NQPAD], active cols = nq[b].
// ---------------------------------------------------------------------------
#define SMX_IT ((NQPAD + 255) / 256)   // 5
__global__ void __launch_bounds__(256) softmax_kernel(
    const float* __restrict__ S, const int* __restrict__ nq_arr,
    __half* __restrict__ ah, __half* __restrict__ al)
{
    const size_t row = blockIdx.x;
    const int b = (int)(row / PD);
    const float* s = S + row * NQPAD;
    const int nq = nq_arr[b];

    __shared__ float red[256];
    const int tid = threadIdx.x;

    float vals[SMX_IT];
    float m = -INFINITY;
#pragma unroll
    for (int i = 0; i < SMX_IT; i++) {
        int qq = tid + i * 256;
        vals[i] = (qq < NQPAD) ? s[qq] : 0.f;
        if (qq < nq) m = fmaxf(m, vals[i]);
    }
    red[tid] = m;
    __syncthreads();
    for (int st = 128; st > 0; st >>= 1) {
        if (tid < st) red[tid] = fmaxf(red[tid], red[tid + st]);
        __syncthreads();
    }
    m = red[0];
    __syncthreads();

    float sum = 0.f;
#pragma unroll
    for (int i = 0; i < SMX_IT; i++) {
        int qq = tid + i * 256;
        float e = (qq < nq) ? expf(vals[i] - m) : 0.f;
        vals[i] = e;
        sum += e;
    }
    red[tid] = sum;
    __syncthreads();
    for (int st = 128; st > 0; st >>= 1) {
        if (tid < st) red[tid] += red[tid + st];
        __syncthreads();
    }
    sum = red[0];

    const float inv = (sum > 0.f) ? (1.f / sum) : 0.f;
#pragma unroll
    for (int i = 0; i < SMX_IT; i++) {
        int qq = tid + i * 256;
        if (qq < NQPAD) {
            float a = vals[i] * inv;
            __half h = __float2half_rn(a);
            __half l = __float2half_rn(a - __half2float(h));
            ah[row * NQPAD + qq] = h;
            al[row * NQPAD + qq] = l;
        }
    }
}

// ---------------------------------------------------------------------------
extern "C" void kernel_launch(void* const* d_in, const int* in_sizes, int n_in,
                              void* d_out, int out_size)
{
    const float* passage  = (const float*)d_in[0];  // [B,P,D]
    const float* question = (const float*)d_in[1];  // [B,Q,D]
    const int*   q_mask   = (const int*)  d_in[2];  // [B,Q]
    const float* W_w      = (const float*)d_in[3];  // [D,H]
    const float* W_b      = (const float*)d_in[4];  // [H]
    const float* map_w    = (const float*)d_in[5];  // [H,H]
    const float* map_b    = (const float*)d_in[6];  // [H]
    float* out = (float*)d_out;                     // [B,P,H]

    __half *pass_h, *pass_l, *qc_h, *qc_l, *Wt_h, *Wt_l, *mT_h, *mT_l;
    __half *Wp_h, *Wp_l, *Wq_h, *Wq_l, *WqT_h, *WqT_l, *al_h, *al_l, *O_h, *O_l;
    float* S;
    int *idx, *nq;
    cudaGetSymbolAddress((void**)&pass_h, g_pass_h);
    cudaGetSymbolAddress((void**)&pass_l, g_pass_l);
    cudaGetSymbolAddress((void**)&qc_h, g_qc_h);
    cudaGetSymbolAddress((void**)&qc_l, g_qc_l);
    cudaGetSymbolAddress((void**)&Wt_h, g_Wt_h);
    cudaGetSymbolAddress((void**)&Wt_l, g_Wt_l);
    cudaGetSymbolAddress((void**)&mT_h, g_mT_h);
    cudaGetSymbolAddress((void**)&mT_l, g_mT_l);
    cudaGetSymbolAddress((void**)&Wp_h, g_Wp_h);
    cudaGetSymbolAddress((void**)&Wp_l, g_Wp_l);
    cudaGetSymbolAddress((void**)&Wq_h, g_Wq_h);
    cudaGetSymbolAddress((void**)&Wq_l, g_Wq_l);
    cudaGetSymbolAddress((void**)&WqT_h, g_WqT_h);
    cudaGetSymbolAddress((void**)&WqT_l, g_WqT_l);
    cudaGetSymbolAddress((void**)&S, g_S);
    cudaGetSymbolAddress((void**)&al_h, g_al_h);
    cudaGetSymbolAddress((void**)&al_l, g_al_l);
    cudaGetSymbolAddress((void**)&O_h, g_O_h);
    cudaGetSymbolAddress((void**)&O_l, g_O_l);
    cudaGetSymbolAddress((void**)&idx, g_idx);
    cudaGetSymbolAddress((void**)&nq, g_nq);

    static bool attr_set = false;
    if (!attr_set) {
        cudaFuncSetAttribute(hgemm_kernel<128, 256, true, true, false>,
                             cudaFuncAttributeMaxDynamicSharedMemorySize, GEMM_SMEM);
        cudaFuncSetAttribute(hgemm_kernel<256, 128, false, false, false>,
                             cudaFuncAttributeMaxDynamicSharedMemorySize, GEMM_SMEM);
        cudaFuncSetAttribute(hgemm_kernel<128, 256, true, false, false>,
                             cudaFuncAttributeMaxDynamicSharedMemorySize, GEMM_SMEM);
        cudaFuncSetAttribute(hgemm_kernel<128, 256, false, true, true>,
                             cudaFuncAttributeMaxDynamicSharedMemorySize, GEMM_SMEM);
        attr_set = true;
    }

    dim3 blk(256);

    // mask scan + compact gather of question
    mask_scan_kernel<<<BD, blk>>>(q_mask, idx, nq);
    gather_split_kernel<<<BD * NQPAD, blk>>>(question, idx, nq, qc_h, qc_l);

    // splits + transposed/split weights
    split_kernel<<<(BP * (size_t)DD) / 1024, blk>>>(passage, pass_h, pass_l);
    transpose_split_kernel<<<dim3(HD / 32, DD / 32), blk>>>(W_w, Wt_h, Wt_l, DD, HD);
    transpose_split_kernel<<<dim3(HD / 32, HD / 32), blk>>>(map_w, mT_h, mT_l, HD, HD);

    // Wp = passage @ W_w + W_b  -> split out  [BP, H]
    hgemm_kernel<128, 256, true, true, false>
        <<<dim3(HD / 256, BP / 128, 1), blk, GEMM_SMEM>>>(
        pass_h, pass_l, Wt_h, Wt_l, W_b, nullptr, Wp_h, Wp_l, DD, HD, 0, 0, 0);

    // Wq' = qc @ W_w + W_b -> split out  [B*NQPAD, H]
    hgemm_kernel<128, 256, true, true, false>
        <<<dim3(HD / 256, (BD * NQPAD) / 128, 1), blk, GEMM_SMEM>>>(
        qc_h, qc_l, Wt_h, Wt_l, W_b, nullptr, Wq_h, Wq_l, DD, HD, 0, 0, 0);

    // WqT'[b] = Wq'[b]^T  [H, NQPAD]
    transpose_pair_kernel<<<dim3(HD / 32, NQPAD / 32, BD), blk>>>(
        Wq_h, Wq_l, WqT_h, WqT_l, NQPAD, HD, (size_t)NQPAD * HD, (size_t)HD * NQPAD);

    // S'[b] = Wp[b] @ Wq'[b]^T  -> fp32  [P, NQPAD]   (256x128 tiles)
    hgemm_kernel<256, 128, false, false, false>
        <<<dim3(NQPAD / 128, PD / 256, BD), blk, GEMM_SMEM>>>(
        Wp_h, Wp_l, Wq_h, Wq_l, nullptr, S, nullptr, nullptr, HD, NQPAD,
        (size_t)PD * HD, (size_t)NQPAD * HD, (size_t)PD * NQPAD);

    // softmax over active cols -> split alpha (pad cols zero)
    softmax_kernel<<<BP, blk>>>(S, nq, al_h, al_l);

    // O[b] = alpha'[b] @ Wq'[b]  -> split out  [P, H]
    hgemm_kernel<128, 256, true, false, false>
        <<<dim3(HD / 256, PD / 128, BD), blk, GEMM_SMEM>>>(
        al_h, al_l, WqT_h, WqT_l, nullptr, nullptr, O_h, O_l, NQPAD, HD,
        (size_t)PD * NQPAD, (size_t)HD * NQPAD, (size_t)PD * HD);

    // out = relu(O @ map_w + map_b) -> fp32 d_out
    hgemm_kernel<128, 256, false, true, true>
        <<<dim3(HD / 256, BP / 128, 1), blk, GEMM_SMEM>>>(
        O_h, O_l, mT_h, mT_l, map_b, out, nullptr, nullptr, HD, HD, 0, 0, 0);
}

// round 7
// speedup vs baseline: 4.1346x; 1.1277x over previous
#include <cuda_runtime.h>
#include <cuda_fp16.h>
#include <math.h>
#include <stdint.h>

// Problem dims (fixed)
#define BD 16
#define PD 2048
#define QD 2048
#define DD 1024
#define HD 1024
#define BP (BD * PD)   // 32768
#define NQPAD 1152     // compacted question length, padded (9 * 128)

// ---------------------------------------------------------------------------
// Scratch (allocation-free: __device__ globals)
// ---------------------------------------------------------------------------
__device__ __half g_pass_h [(size_t)BP * DD];
__device__ __half g_pass_l [(size_t)BP * DD];
__device__ __half g_qc_h   [(size_t)BD * NQPAD * DD];   // compacted question
__device__ __half g_qc_l   [(size_t)BD * NQPAD * DD];
__device__ __half g_Wt_h   [(size_t)HD * DD];           // W_w^T
__device__ __half g_Wt_l   [(size_t)HD * DD];
__device__ __half g_mT_h   [(size_t)HD * HD];           // map_w^T
__device__ __half g_mT_l   [(size_t)HD * HD];
__device__ __half g_Wp_h   [(size_t)BP * HD];
__device__ __half g_Wp_l   [(size_t)BP * HD];
__device__ __half g_Wq_h   [(size_t)BD * NQPAD * HD];   // compacted Wq
__device__ __half g_Wq_l   [(size_t)BD * NQPAD * HD];
__device__ __half g_WqT_h  [(size_t)BD * HD * NQPAD];
__device__ __half g_WqT_l  [(size_t)BD * HD * NQPAD];
__device__ float  g_S      [(size_t)BP * NQPAD];        // 151 MB
__device__ __half g_al_h   [(size_t)BP * NQPAD];        // alpha (fp16 only)
__device__ __half g_O_h    [(size_t)BP * HD];           // O (fp16 only)
__device__ int    g_idx    [(size_t)BD * QD];
__device__ int    g_nq     [BD];

// ---------------------------------------------------------------------------
// PTX helpers (all Ampere-era: no arch-suffix gating)
// ---------------------------------------------------------------------------
__device__ __forceinline__ uint32_t smem_u32(const void* p) {
    uint32_t a;
    asm("{ .reg .u64 t; cvta.to.shared.u64 t, %1; cvt.u32.u64 %0, t; }"
        : "=r"(a) : "l"(p));
    return a;
}

__device__ __forceinline__ void cp_async16(uint32_t dst, const void* src) {
    asm volatile("cp.async.cg.shared.global [%0], [%1], 16;"
                 :: "r"(dst), "l"(src));
}
#define CP_COMMIT() asm volatile("cp.async.commit_group;")
#define CP_WAIT1()  asm volatile("cp.async.wait_group 1;")

__device__ __forceinline__ void ldsm4(uint32_t& r0, uint32_t& r1,
                                      uint32_t& r2, uint32_t& r3, uint32_t addr) {
    asm volatile("ldmatrix.sync.aligned.m8n8.x4.shared.b16 {%0,%1,%2,%3}, [%4];"
                 : "=r"(r0), "=r"(r1), "=r"(r2), "=r"(r3) : "r"(addr));
}

__device__ __forceinline__ void mma16816(float c[4], const uint32_t a[4],
                                         uint32_t b0, uint32_t b1) {
    asm volatile(
        "mma.sync.aligned.m16n8k16.row.col.f32.f16.f16.f32 "
        "{%0,%1,%2,%3}, {%4,%5,%6,%7}, {%8,%9}, {%0,%1,%2,%3};"
        : "+f"(c[0]), "+f"(c[1]), "+f"(c[2]), "+f"(c[3])
        : "r"(a[0]), "r"(a[1]), "r"(a[2]), "r"(a[3]), "r"(b0), "r"(b1));
}

// ---------------------------------------------------------------------------
// HGEMM split-fp16: C[M,N] = A[M,K] * B[N,K]^T  (NT, K-major fp16)
// TERMS=3: ah*bh + ah*bl + al*bh (score path)
// TERMS=2: ah*bh + ah*bl         (A rounded to fp16; post-softmax path)
// OUTM: 0 = fp32, 1 = split (h+l), 2 = fp16 h only
// Block BM x BN, 256 threads, warp tile 64x64, K-block 32, 3-stage cp.async.
// SMEM rows padded to 80B -> conflict-free ldmatrix without XOR.
// ---------------------------------------------------------------------------
#define NSTAGE   3
#define GEMM_SMEM 184320    // worst case: (2*BM+2*BN)*80*3 with BM+BN=384

template <int BM, int BN, int TERMS>
__device__ __forceinline__ void stage_load(
    uint32_t sbase, const __half* Ahb, const __half* Alb,
    const __half* Bhb, const __half* Blb, int kb, int K, int tid)
{
    constexpr int NA  = (TERMS == 3 ? BM * 8 : BM * 4);   // A-region chunk count
    constexpr int TOT = NA + BN * 8;
#pragma unroll
    for (int u = 0; u < TOT / 256; u++) {
        int i = tid + u * 256;
        const __half* src;
        uint32_t dst;
        if (i < BM * 4) {
            int r = i >> 2, c = i & 3;
            src = Ahb + (size_t)r * K + kb * 32 + c * 8;
            dst = sbase + r * 80 + c * 16;
        } else if (TERMS == 3 && i < BM * 8) {
            int j = i - BM * 4; int r = j >> 2, c = j & 3;
            src = Alb + (size_t)r * K + kb * 32 + c * 8;
            dst = sbase + BM * 80 + r * 80 + c * 16;
        } else if (i < NA + BN * 4) {
            int j = i - NA; int r = j >> 2, c = j & 3;
            src = Bhb + (size_t)r * K + kb * 32 + c * 8;
            dst = sbase + (TERMS == 3 ? 2 : 1) * BM * 80 + r * 80 + c * 16;
        } else {
            int j = i - NA - BN * 4; int r = j >> 2, c = j & 3;
            src = Blb + (size_t)r * K + kb * 32 + c * 8;
            dst = sbase + (TERMS == 3 ? 2 : 1) * BM * 80 + BN * 80 + r * 80 + c * 16;
        }
        cp_async16(dst, src);
    }
}

template <int BM, int BN, int TERMS, int OUTM, bool BIAS, bool RELU>
__global__ void __launch_bounds__(256, 1) hgemm_kernel(
    const __half* __restrict__ Ah, const __half* __restrict__ Al,
    const __half* __restrict__ Bh, const __half* __restrict__ Bl,
    const float* __restrict__ bias,
    float* __restrict__ Cf, __half* __restrict__ Ch, __half* __restrict__ Cl,
    int K, int N, size_t sA, size_t sB, size_t sC)
{
    extern __shared__ char smem[];
    const uint32_t smem_base = smem_u32(smem);

    constexpr int SBYTES = ((TERMS == 3 ? 2 : 1) * BM + 2 * BN) * 80;
    constexpr int WN = BN / 64;         // warps along N
    const int tid  = threadIdx.x;
    const int lane = tid & 31;
    const int wid  = tid >> 5;
    const int wm   = wid / WN;
    const int wn   = wid % WN;
    const int bm   = blockIdx.y * BM;
    const int bn   = blockIdx.x * BN;

    const __half* Ahb = Ah + (size_t)blockIdx.z * sA + (size_t)bm * K;
    const __half* Alb = (TERMS == 3)
        ? Al + (size_t)blockIdx.z * sA + (size_t)bm * K : nullptr;
    const __half* Bhb = Bh + (size_t)blockIdx.z * sB + (size_t)bn * K;
    const __half* Blb = Bl + (size_t)blockIdx.z * sB + (size_t)bn * K;

    float acc[4][8][4];
#pragma unroll
    for (int i = 0; i < 4; i++)
#pragma unroll
        for (int j = 0; j < 8; j++)
#pragma unroll
            for (int r = 0; r < 4; r++) acc[i][j][r] = 0.f;

    const int nk = K / 32;

    // prologue: stages 0,1
#pragma unroll
    for (int s = 0; s < NSTAGE - 1; s++) {
        stage_load<BM, BN, TERMS>(smem_base + s * SBYTES, Ahb, Alb, Bhb, Blb, s, K, tid);
        CP_COMMIT();
    }

    // lane-invariant fragment offsets
    const uint32_t a_off = (uint32_t)((wm * 64 + (lane & 15)) * 80 + (lane >> 4) * 16);
    const int q = lane >> 3;
    const uint32_t b_off = (uint32_t)((wn * 64 + (q >> 1) * 8 + (lane & 7)) * 80
                                      + (q & 1) * 16);

    int sidx = 0;
    for (int kb = 0; kb < nk; kb++) {
        CP_WAIT1();
        __syncthreads();

        if (kb + NSTAGE - 1 < nk) {
            int ls = sidx + (NSTAGE - 1); if (ls >= NSTAGE) ls -= NSTAGE;
            stage_load<BM, BN, TERMS>(smem_base + ls * SBYTES,
                                      Ahb, Alb, Bhb, Blb, kb + NSTAGE - 1, K, tid);
        }
        CP_COMMIT();

        const uint32_t sb = smem_base + sidx * SBYTES;
        const uint32_t sa_h = sb;
        const uint32_t sa_l = sb + BM * 80;                       // TERMS==3 only
        const uint32_t sb_h = sb + (TERMS == 3 ? 2 : 1) * BM * 80;
        const uint32_t sb_l = sb_h + BN * 80;

#pragma unroll
        for (int kk = 0; kk < 2; kk++) {
            uint32_t ah[4][4], alr[4][4];
#pragma unroll
            for (int i = 0; i < 4; i++) {
                ldsm4(ah[i][0], ah[i][1], ah[i][2], ah[i][3],
                      sa_h + a_off + i * 1280 + kk * 32);
                if (TERMS == 3)
                    ldsm4(alr[i][0], alr[i][1], alr[i][2], alr[i][3],
                          sa_l + a_off + i * 1280 + kk * 32);
            }
            uint32_t bh[8][2], bl[8][2];
#pragma unroll
            for (int jp = 0; jp < 8; jp += 2) {
                ldsm4(bh[jp][0], bh[jp][1], bh[jp + 1][0], bh[jp + 1][1],
                      sb_h + b_off + jp * 640 + kk * 32);
                ldsm4(bl[jp][0], bl[jp][1], bl[jp + 1][0], bl[jp + 1][1],
                      sb_l + b_off + jp * 640 + kk * 32);
            }
#pragma unroll
            for (int i = 0; i < 4; i++)
#pragma unroll
                for (int j = 0; j < 8; j++) {
                    mma16816(acc[i][j], ah[i], bh[j][0], bh[j][1]);
                    mma16816(acc[i][j], ah[i], bl[j][0], bl[j][1]);
                    if (TERMS == 3)
                        mma16816(acc[i][j], alr[i], bh[j][0], bh[j][1]);
                }
        }
        if (++sidx >= NSTAGE) sidx = 0;
    }

    // ---- epilogue
#pragma unroll
    for (int i = 0; i < 4; i++) {
        const int row0 = bm + wm * 64 + i * 16 + (lane >> 2);
        const size_t b0 = (size_t)blockIdx.z * sC + (size_t)row0 * N;
        const size_t b1 = b0 + (size_t)8 * N;
#pragma unroll
        for (int j = 0; j < 8; j++) {
            const int col = bn + wn * 64 + j * 8 + 2 * (lane & 3);
            float c0 = acc[i][j][0], c1 = acc[i][j][1];
            float c2 = acc[i][j][2], c3 = acc[i][j][3];
            if (BIAS) {
                const float bb0 = bias[col], bb1 = bias[col + 1];
                c0 += bb0; c1 += bb1; c2 += bb0; c3 += bb1;
            }
            if (RELU) {
                c0 = fmaxf(c0, 0.f); c1 = fmaxf(c1, 0.f);
                c2 = fmaxf(c2, 0.f); c3 = fmaxf(c3, 0.f);
            }
            if (OUTM == 0) {
                *(float2*)(Cf + b0 + col) = make_float2(c0, c1);
                *(float2*)(Cf + b1 + col) = make_float2(c2, c3);
            } else {
                __half h0 = __float2half_rn(c0), h1 = __float2half_rn(c1);
                __half h2 = __float2half_rn(c2), h3 = __float2half_rn(c3);
                *(__half2*)(Ch + b0 + col) = __halves2half2(h0, h1);
                *(__half2*)(Ch + b1 + col) = __halves2half2(h2, h3);
                if (OUTM == 1) {
                    __half l0 = __float2half_rn(c0 - __half2float(h0));
                    __half l1 = __float2half_rn(c1 - __half2float(h1));
                    __half l2 = __float2half_rn(c2 - __half2float(h2));
                    __half l3 = __float2half_rn(c3 - __half2float(h3));
                    *(__half2*)(Cl + b0 + col) = __halves2half2(l0, l1);
                    *(__half2*)(Cl + b1 + col) = __halves2half2(l2, l3);
                }
            }
        }
    }
}

// ---------------------------------------------------------------------------
// Elementwise fp32 -> (hi, lo) fp16 split.
// ---------------------------------------------------------------------------
__global__ void __launch_bounds__(256) split_kernel(
    const float* __restrict__ in, __half* __restrict__ oh,
    __half* __restrict__ ol)
{
    const size_t idx = (size_t)blockIdx.x * 256 + threadIdx.x;
    float4 v = ((const float4*)in)[idx];
    __half h0 = __float2half_rn(v.x), h1 = __float2half_rn(v.y);
    __half h2 = __float2half_rn(v.z), h3 = __float2half_rn(v.w);
    __half l0 = __float2half_rn(v.x - __half2float(h0));
    __half l1 = __float2half_rn(v.y - __half2float(h1));
    __half l2 = __float2half_rn(v.z - __half2float(h2));
    __half l3 = __float2half_rn(v.w - __half2float(h3));
    ((__half2*)oh)[idx * 2]     = __halves2half2(h0, h1);
    ((__half2*)oh)[idx * 2 + 1] = __halves2half2(h2, h3);
    ((__half2*)ol)[idx * 2]     = __halves2half2(l0, l1);
    ((__half2*)ol)[idx * 2 + 1] = __halves2half2(l2, l3);
}

// ---------------------------------------------------------------------------
// Transpose + split: fp32 in[R][C] -> oh/ol [C][R] fp16
// ---------------------------------------------------------------------------
__global__ void __launch_bounds__(256) transpose_split_kernel(
    const float* __restrict__ in, __half* __restrict__ oh,
    __half* __restrict__ ol, int R, int C)
{
    __shared__ float t[32][33];
    const int c0 = blockIdx.x * 32, r0 = blockIdx.y * 32;
    const int tx = threadIdx.x & 31, ty = threadIdx.x >> 5;
#pragma unroll
    for (int j = 0; j < 4; j++)
        t[ty + j * 8][tx] = in[(size_t)(r0 + ty + j * 8) * C + c0 + tx];
    __syncthreads();
#pragma unroll
    for (int j = 0; j < 4; j++) {
        float v = t[tx][ty + j * 8];
        __half h = __float2half_rn(v);
        __half l = __float2half_rn(v - __half2float(h));
        size_t o = (size_t)(c0 + ty + j * 8) * R + r0 + tx;
        oh[o] = h;
        ol[o] = l;
    }
}

// ---------------------------------------------------------------------------
// Transpose fp16 pair: ih/il [R][C] -> oh/ol [C][R], batched via blockIdx.z
// ---------------------------------------------------------------------------
__global__ void __launch_bounds__(256) transpose_pair_kernel(
    const __half* __restrict__ ih, const __half* __restrict__ il,
    __half* __restrict__ oh, __half* __restrict__ ol,
    int R, int C, size_t sin, size_t sout)
{
    __shared__ __half th[32][33];
    __shared__ __half tl[32][33];
    ih += (size_t)blockIdx.z * sin;  il += (size_t)blockIdx.z * sin;
    oh += (size_t)blockIdx.z * sout; ol += (size_t)blockIdx.z * sout;
    const int c0 = blockIdx.x * 32, r0 = blockIdx.y * 32;
    const int tx = threadIdx.x & 31, ty = threadIdx.x >> 5;
#pragma unroll
    for (int j = 0; j < 4; j++) {
        size_t src = (size_t)(r0 + ty + j * 8) * C + c0 + tx;
        th[ty + j * 8][tx] = ih[src];
        tl[ty + j * 8][tx] = il[src];
    }
    __syncthreads();
#pragma unroll
    for (int j = 0; j < 4; j++) {
        size_t dst = (size_t)(c0 + ty + j * 8) * R + r0 + tx;
        oh[dst] = th[tx][ty + j * 8];
        ol[dst] = tl[tx][ty + j * 8];
    }
}

// ---------------------------------------------------------------------------
// Per-batch deterministic mask scan: active q indices + count.
// ---------------------------------------------------------------------------
__global__ void __launch_bounds__(256) mask_scan_kernel(
    const int* __restrict__ qmask, int* __restrict__ idx, int* __restrict__ nq)
{
    const int b = blockIdx.x;
    const int* m = qmask + (size_t)b * QD;
    __shared__ int cnt[256];
    const int tid = threadIdx.x;

    int loc[8];
    int c = 0;
#pragma unroll
    for (int j = 0; j < 8; j++) {
        loc[j] = m[tid * 8 + j];
        c += loc[j];
    }
    cnt[tid] = c;
    __syncthreads();
    for (int off = 1; off < 256; off <<= 1) {
        int v = (tid >= off) ? cnt[tid - off] : 0;
        __syncthreads();
        cnt[tid] += v;
        __syncthreads();
    }
    int base = cnt[tid] - c;   // exclusive
#pragma unroll
    for (int j = 0; j < 8; j++) {
        if (loc[j]) {
            if (base < NQPAD) idx[(size_t)b * QD + base] = tid * 8 + j;
            base++;
        }
    }
    if (tid == 255) nq[b] = cnt[255] < NQPAD ? cnt[255] : NQPAD;
}

// ---------------------------------------------------------------------------
// Gather active question rows + split to fp16 pair; pad rows -> zeros.
// ---------------------------------------------------------------------------
__global__ void __launch_bounds__(256) gather_split_kernel(
    const float* __restrict__ question, const int* __restrict__ idx,
    const int* __restrict__ nq, __half* __restrict__ oh, __half* __restrict__ ol)
{
    const int r = blockIdx.x % NQPAD;
    const int b = blockIdx.x / NQPAD;
    const int tid = threadIdx.x;
    const size_t dst = ((size_t)b * NQPAD + r) * DD + tid * 4;

    if (r < nq[b]) {
        const int src_row = idx[(size_t)b * QD + r];
        float4 v = *(const float4*)(question + ((size_t)b * QD + src_row) * DD + tid * 4);
        __half h0 = __float2half_rn(v.x), h1 = __float2half_rn(v.y);
        __half h2 = __float2half_rn(v.z), h3 = __float2half_rn(v.w);
        __half l0 = __float2half_rn(v.x - __half2float(h0));
        __half l1 = __float2half_rn(v.y - __half2float(h1));
        __half l2 = __float2half_rn(v.z - __half2float(h2));
        __half l3 = __float2half_rn(v.w - __half2float(h3));
        *(__half2*)(oh + dst)     = __halves2half2(h0, h1);
        *(__half2*)(oh + dst + 2) = __halves2half2(h2, h3);
        *(__half2*)(ol + dst)     = __halves2half2(l0, l1);
        *(__half2*)(ol + dst + 2) = __halves2half2(l2, l3);
    } else {
        *(float2*)(oh + dst) = make_float2(0.f, 0.f);
        *(float2*)(ol + dst) = make_float2(0.f, 0.f);
    }
}

// ---------------------------------------------------------------------------
// Softmax over compacted rows S[BP, NQPAD], active cols = nq[b].
// Writes fp16 alpha (no low part — consumed by 2-term GEMM).
// ---------------------------------------------------------------------------
#define SMX_IT ((NQPAD + 255) / 256)   // 5
__global__ void __launch_bounds__(256) softmax_kernel(
    const float* __restrict__ S, const int* __restrict__ nq_arr,
    __half* __restrict__ ah)
{
    const size_t row = blockIdx.x;
    const int b = (int)(row / PD);
    const float* s = S + row * NQPAD;
    const int nq = nq_arr[b];

    __shared__ float red[256];
    const int tid = threadIdx.x;

    float vals[SMX_IT];
    float m = -INFINITY;
#pragma unroll
    for (int i = 0; i < SMX_IT; i++) {
        int qq = tid + i * 256;
        vals[i] = (qq < NQPAD) ? s[qq] : 0.f;
        if (qq < nq) m = fmaxf(m, vals[i]);
    }
    red[tid] = m;
    __syncthreads();
    for (int st = 128; st > 0; st >>= 1) {
        if (tid < st) red[tid] = fmaxf(red[tid], red[tid + st]);
        __syncthreads();
    }
    m = red[0];
    __syncthreads();

    float sum = 0.f;
#pragma unroll
    for (int i = 0; i < SMX_IT; i++) {
        int qq = tid + i * 256;
        float e = (qq < nq) ? expf(vals[i] - m) : 0.f;
        vals[i] = e;
        sum += e;
    }
    red[tid] = sum;
    __syncthreads();
    for (int st = 128; st > 0; st >>= 1) {
        if (tid < st) red[tid] += red[tid + st];
        __syncthreads();
    }
    sum = red[0];

    const float inv = (sum > 0.f) ? (1.f / sum) : 0.f;
#pragma unroll
    for (int i = 0; i < SMX_IT; i++) {
        int qq = tid + i * 256;
        if (qq < NQPAD)
            ah[row * NQPAD + qq] = __float2half_rn(vals[i] * inv);
    }
}

// ---------------------------------------------------------------------------
extern "C" void kernel_launch(void* const* d_in, const int* in_sizes, int n_in,
                              void* d_out, int out_size)
{
    const float* passage  = (const float*)d_in[0];  // [B,P,D]
    const float* question = (const float*)d_in[1];  // [B,Q,D]
    const int*   q_mask   = (const int*)  d_in[2];  // [B,Q]
    const float* W_w      = (const float*)d_in[3];  // [D,H]
    const float* W_b      = (const float*)d_in[4];  // [H]
    const float* map_w    = (const float*)d_in[5];  // [H,H]
    const float* map_b    = (const float*)d_in[6];  // [H]
    float* out = (float*)d_out;                     // [B,P,H]

    __half *pass_h, *pass_l, *qc_h, *qc_l, *Wt_h, *Wt_l, *mT_h, *mT_l;
    __half *Wp_h, *Wp_l, *Wq_h, *Wq_l, *WqT_h, *WqT_l, *al_h, *O_h;
    float* S;
    int *idx, *nq;
    cudaGetSymbolAddress((void**)&pass_h, g_pass_h);
    cudaGetSymbolAddress((void**)&pass_l, g_pass_l);
    cudaGetSymbolAddress((void**)&qc_h, g_qc_h);
    cudaGetSymbolAddress((void**)&qc_l, g_qc_l);
    cudaGetSymbolAddress((void**)&Wt_h, g_Wt_h);
    cudaGetSymbolAddress((void**)&Wt_l, g_Wt_l);
    cudaGetSymbolAddress((void**)&mT_h, g_mT_h);
    cudaGetSymbolAddress((void**)&mT_l, g_mT_l);
    cudaGetSymbolAddress((void**)&Wp_h, g_Wp_h);
    cudaGetSymbolAddress((void**)&Wp_l, g_Wp_l);
    cudaGetSymbolAddress((void**)&Wq_h, g_Wq_h);
    cudaGetSymbolAddress((void**)&Wq_l, g_Wq_l);
    cudaGetSymbolAddress((void**)&WqT_h, g_WqT_h);
    cudaGetSymbolAddress((void**)&WqT_l, g_WqT_l);
    cudaGetSymbolAddress((void**)&S, g_S);
    cudaGetSymbolAddress((void**)&al_h, g_al_h);
    cudaGetSymbolAddress((void**)&O_h, g_O_h);
    cudaGetSymbolAddress((void**)&idx, g_idx);
    cudaGetSymbolAddress((void**)&nq, g_nq);

    static bool attr_set = false;
    if (!attr_set) {
        cudaFuncSetAttribute((const void*)hgemm_kernel<128, 256, 3, 1, true, false>,
                             cudaFuncAttributeMaxDynamicSharedMemorySize, GEMM_SMEM);
        cudaFuncSetAttribute((const void*)hgemm_kernel<256, 128, 3, 0, false, false>,
                             cudaFuncAttributeMaxDynamicSharedMemorySize, GEMM_SMEM);
        cudaFuncSetAttribute((const void*)hgemm_kernel<128, 256, 2, 2, false, false>,
                             cudaFuncAttributeMaxDynamicSharedMemorySize, GEMM_SMEM);
        cudaFuncSetAttribute((const void*)hgemm_kernel<128, 256, 2, 0, true, true>,
                             cudaFuncAttributeMaxDynamicSharedMemorySize, GEMM_SMEM);
        attr_set = true;
    }

    dim3 blk(256);

    // mask scan + compact gather of question
    mask_scan_kernel<<<BD, blk>>>(q_mask, idx, nq);
    gather_split_kernel<<<BD * NQPAD, blk>>>(question, idx, nq, qc_h, qc_l);

    // splits + transposed/split weights
    split_kernel<<<(BP * (size_t)DD) / 1024, blk>>>(passage, pass_h, pass_l);
    transpose_split_kernel<<<dim3(HD / 32, DD / 32), blk>>>(W_w, Wt_h, Wt_l, DD, HD);
    transpose_split_kernel<<<dim3(HD / 32, HD / 32), blk>>>(map_w, mT_h, mT_l, HD, HD);

    // Wp = passage @ W_w + W_b  -> split out  [BP, H]   (3-term, score path)
    hgemm_kernel<128, 256, 3, 1, true, false>
        <<<dim3(HD / 256, BP / 128, 1), blk, GEMM_SMEM>>>(
        pass_h, pass_l, Wt_h, Wt_l, W_b, nullptr, Wp_h, Wp_l, DD, HD, 0, 0, 0);

    // Wq' = qc @ W_w + W_b -> split out  [B*NQPAD, H]   (3-term, score path)
    hgemm_kernel<128, 256, 3, 1, true, false>
        <<<dim3(HD / 256, (BD * NQPAD) / 128, 1), blk, GEMM_SMEM>>>(
        qc_h, qc_l, Wt_h, Wt_l, W_b, nullptr, Wq_h, Wq_l, DD, HD, 0, 0, 0);

    // WqT'[b] = Wq'[b]^T  [H, NQPAD]
    transpose_pair_kernel<<<dim3(HD / 32, NQPAD / 32, BD), blk>>>(
        Wq_h, Wq_l, WqT_h, WqT_l, NQPAD, HD, (size_t)NQPAD * HD, (size_t)HD * NQPAD);

    // S'[b] = Wp[b] @ Wq'[b]^T  -> fp32  [P, NQPAD]  (3-term, 256x128 tiles)
    hgemm_kernel<256, 128, 3, 0, false, false>
        <<<dim3(NQPAD / 128, PD / 256, BD), blk, GEMM_SMEM>>>(
        Wp_h, Wp_l, Wq_h, Wq_l, nullptr, S, nullptr, nullptr, HD, NQPAD,
        (size_t)PD * HD, (size_t)NQPAD * HD, (size_t)PD * NQPAD);

    // softmax over active cols -> fp16 alpha
    softmax_kernel<<<BP, blk>>>(S, nq, al_h);

    // O[b] = alpha'[b] @ Wq'[b]  -> fp16 O  [P, H]   (2-term: alpha fp16)
    hgemm_kernel<128, 256, 2, 2, false, false>
        <<<dim3(HD / 256, PD / 128, BD), blk, GEMM_SMEM>>>(
        al_h, nullptr, WqT_h, WqT_l, nullptr, nullptr, O_h, nullptr, NQPAD, HD,
        (size_t)PD * NQPAD, (size_t)HD * NQPAD, (size_t)PD * HD);

    // out = relu(O @ map_w + map_b) -> fp32 d_out   (2-term: O fp16)
    hgemm_kernel<128, 256, 2, 0, true, true>
        <<<dim3(HD / 256, BP / 128, 1), blk, GEMM_SMEM>>>(
        O_h, nullptr, mT_h, mT_l, map_b, out, nullptr, nullptr, HD, HD, 0, 0, 0);
}

// round 12
// speedup vs baseline: 4.8208x; 1.1660x over previous
#include <cuda_runtime.h>
#include <cuda_fp16.h>
#include <math.h>
#include <stdint.h>

// Problem dims (fixed)
#define BD 16
#define PD 2048
#define QD 2048
#define DD 1024
#define HD 1024
#define BP (BD * PD)   // 32768
#define NQPAD 1152     // compacted question length, padded (9 * 128)

// ---------------------------------------------------------------------------
// Scratch (allocation-free: __device__ globals)
// ---------------------------------------------------------------------------
__device__ __half g_pass_h [(size_t)BP * DD];           // passage split
__device__ __half g_pass_l [(size_t)BP * DD];
__device__ __half g_qc_h   [(size_t)BD * NQPAD * DD];   // compacted question split
__device__ __half g_qc_l   [(size_t)BD * NQPAD * DD];
__device__ __half g_Wt_h   [(size_t)HD * DD];           // W_w^T split
__device__ __half g_Wt_l   [(size_t)HD * DD];
__device__ __half g_mT_h   [(size_t)HD * HD];           // map_w^T (fp16 hi only)
__device__ __half g_Wp_h   [(size_t)BP * HD];
__device__ __half g_Wp_l   [(size_t)BP * HD];
__device__ __half g_Wq_h   [(size_t)BD * NQPAD * HD];   // compacted Wq split
__device__ __half g_Wq_l   [(size_t)BD * NQPAD * HD];
__device__ __half g_WqT_h  [(size_t)BD * HD * NQPAD];   // transposed hi only
__device__ float  g_S      [(size_t)BP * NQPAD];        // 151 MB
__device__ __half g_al_h   [(size_t)BP * NQPAD];        // alpha (fp16 only)
__device__ __half g_O_h    [(size_t)BP * HD];           // O (fp16 only)
__device__ int    g_idx    [(size_t)BD * QD];
__device__ int    g_nq     [BD];

// ---------------------------------------------------------------------------
// PTX helpers (all Ampere-era: no arch-suffix gating)
// ---------------------------------------------------------------------------
__device__ __forceinline__ uint32_t smem_u32(const void* p) {
    uint32_t a;
    asm("{ .reg .u64 t; cvta.to.shared.u64 t, %1; cvt.u32.u64 %0, t; }"
        : "=r"(a) : "l"(p));
    return a;
}

__device__ __forceinline__ void cp_async16(uint32_t dst, const void* src) {
    asm volatile("cp.async.cg.shared.global [%0], [%1], 16;"
                 :: "r"(dst), "l"(src));
}
#define CP_COMMIT() asm volatile("cp.async.commit_group;")
template <int N>
__device__ __forceinline__ void cp_wait() {
    asm volatile("cp.async.wait_group %0;" :: "n"(N));
}

__device__ __forceinline__ void ldsm4(uint32_t& r0, uint32_t& r1,
                                      uint32_t& r2, uint32_t& r3, uint32_t addr) {
    asm volatile("ldmatrix.sync.aligned.m8n8.x4.shared.b16 {%0,%1,%2,%3}, [%4];"
                 : "=r"(r0), "=r"(r1), "=r"(r2), "=r"(r3) : "r"(addr));
}

__device__ __forceinline__ void mma16816(float c[4], const uint32_t a[4],
                                         uint32_t b0, uint32_t b1) {
    asm volatile(
        "mma.sync.aligned.m16n8k16.row.col.f32.f16.f16.f32 "
        "{%0,%1,%2,%3}, {%4,%5,%6,%7}, {%8,%9}, {%0,%1,%2,%3};"
        : "+f"(c[0]), "+f"(c[1]), "+f"(c[2]), "+f"(c[3])
        : "r"(a[0]), "r"(a[1]), "r"(a[2]), "r"(a[3]), "r"(b0), "r"(b1));
}

// ---------------------------------------------------------------------------
// HGEMM split-fp16: C[M,N] = A[M,K] * B[N,K]^T  (NT, K-major fp16)
// TERMS=3: ah*bh + ah*bl + al*bh  (score path: A split, B split)
// TERMS=2: ah*bh + ah*bl          (A plain fp16, B split)
// TERMS=1: ah*bh                  (A plain fp16, B plain fp16)
// OUTM: 0 = fp32, 1 = split (h+l), 2 = fp16 h only
// Block BM x BN, 256 threads, warp tile 64x64, K-block 32.
// NSTAGE = 3 (TERMS==3) or 4. SMEM rows padded to 80B -> conflict-free ldmatrix.
// ---------------------------------------------------------------------------
template <int BM, int BN, int TERMS>
struct GemmCfg {
    static constexpr int AP = (TERMS == 3 ? 2 : 1);   // A parts in smem
    static constexpr int BPP = (TERMS >= 2 ? 2 : 1);  // B parts in smem
    static constexpr int SBYTES = (AP * BM + BPP * BN) * 80;
    static constexpr int NST = (TERMS == 3 ? 3 : 4);
    static constexpr int SMEM = SBYTES * NST;
};

template <int BM, int BN, int TERMS>
__device__ __forceinline__ void stage_load(
    uint32_t sbase, const __half* Ahb, const __half* Alb,
    const __half* Bhb, const __half* Blb, int kb, int K, int tid)
{
    constexpr int AP  = GemmCfg<BM, BN, TERMS>::AP;
    constexpr int BPP = GemmCfg<BM, BN, TERMS>::BPP;
    constexpr int NA  = AP * BM * 4;
    constexpr int TOT = NA + BPP * BN * 4;
#pragma unroll
    for (int u = 0; u < TOT / 256; u++) {
        int i = tid + u * 256;
        const __half* src;
        uint32_t dst;
        if (i < BM * 4) {
            int r = i >> 2, c = i & 3;
            src = Ahb + (size_t)r * K + kb * 32 + c * 8;
            dst = sbase + r * 80 + c * 16;
        } else if (AP == 2 && i < BM * 8) {
            int j = i - BM * 4; int r = j >> 2, c = j & 3;
            src = Alb + (size_t)r * K + kb * 32 + c * 8;
            dst = sbase + BM * 80 + r * 80 + c * 16;
        } else if (i < NA + BN * 4) {
            int j = i - NA; int r = j >> 2, c = j & 3;
            src = Bhb + (size_t)r * K + kb * 32 + c * 8;
            dst = sbase + AP * BM * 80 + r * 80 + c * 16;
        } else {
            int j = i - NA - BN * 4; int r = j >> 2, c = j & 3;
            src = Blb + (size_t)r * K + kb * 32 + c * 8;
            dst = sbase + AP * BM * 80 + BN * 80 + r * 80 + c * 16;
        }
        cp_async16(dst, src);
    }
}

template <int BM, int BN, int TERMS, int OUTM, bool BIAS, bool RELU>
__global__ void __launch_bounds__(256, 1) hgemm_kernel(
    const __half* __restrict__ Ah, const __half* __restrict__ Al,
    const __half* __restrict__ Bh, const __half* __restrict__ Bl,
    const float* __restrict__ bias,
    float* __restrict__ Cf, __half* __restrict__ Ch, __half* __restrict__ Cl,
    int K, int N, size_t sA, size_t sB, size_t sC)
{
    extern __shared__ char smem[];
    const uint32_t smem_base = smem_u32(smem);

    using Cfg = GemmCfg<BM, BN, TERMS>;
    constexpr int SBYTES = Cfg::SBYTES;
    constexpr int NST = Cfg::NST;
    constexpr int AP = Cfg::AP;
    constexpr int WN = BN / 64;         // warps along N
    const int tid  = threadIdx.x;
    const int lane = tid & 31;
    const int wid  = tid >> 5;
    const int wm   = wid / WN;
    const int wn   = wid % WN;
    const int bm   = blockIdx.y * BM;
    const int bn   = blockIdx.x * BN;

    const __half* Ahb = Ah + (size_t)blockIdx.z * sA + (size_t)bm * K;
    const __half* Alb = (TERMS == 3)
        ? Al + (size_t)blockIdx.z * sA + (size_t)bm * K : nullptr;
    const __half* Bhb = Bh + (size_t)blockIdx.z * sB + (size_t)bn * K;
    const __half* Blb = (TERMS >= 2)
        ? Bl + (size_t)blockIdx.z * sB + (size_t)bn * K : nullptr;

    float acc[4][8][4];
#pragma unroll
    for (int i = 0; i < 4; i++)
#pragma unroll
        for (int j = 0; j < 8; j++)
#pragma unroll
            for (int r = 0; r < 4; r++) acc[i][j][r] = 0.f;

    const int nk = K / 32;

    // prologue
#pragma unroll
    for (int s = 0; s < NST - 1; s++) {
        stage_load<BM, BN, TERMS>(smem_base + s * SBYTES, Ahb, Alb, Bhb, Blb, s, K, tid);
        CP_COMMIT();
    }

    // lane-invariant fragment offsets
    const uint32_t a_off = (uint32_t)((wm * 64 + (lane & 15)) * 80 + (lane >> 4) * 16);
    const int q = lane >> 3;
    const uint32_t b_off = (uint32_t)((wn * 64 + (q >> 1) * 8 + (lane & 7)) * 80
                                      + (q & 1) * 16);

    int sidx = 0;
    for (int kb = 0; kb < nk; kb++) {
        cp_wait<NST - 2>();
        __syncthreads();

        if (kb + NST - 1 < nk) {
            int ls = sidx + (NST - 1); if (ls >= NST) ls -= NST;
            stage_load<BM, BN, TERMS>(smem_base + ls * SBYTES,
                                      Ahb, Alb, Bhb, Blb, kb + NST - 1, K, tid);
        }
        CP_COMMIT();

        const uint32_t sb = smem_base + sidx * SBYTES;
        const uint32_t sa_h = sb;
        const uint32_t sa_l = sb + BM * 80;            // AP==2 only
        const uint32_t sb_h = sb + AP * BM * 80;
        const uint32_t sb_l = sb_h + BN * 80;          // BPP==2 only

#pragma unroll
        for (int kk = 0; kk < 2; kk++) {
            uint32_t ah[4][4], alr[4][4];
#pragma unroll
            for (int i = 0; i < 4; i++) {
                ldsm4(ah[i][0], ah[i][1], ah[i][2], ah[i][3],
                      sa_h + a_off + i * 1280 + kk * 32);
                if (TERMS == 3)
                    ldsm4(alr[i][0], alr[i][1], alr[i][2], alr[i][3],
                          sa_l + a_off + i * 1280 + kk * 32);
            }
            uint32_t bh[8][2], bl[8][2];
#pragma unroll
            for (int jp = 0; jp < 8; jp += 2) {
                ldsm4(bh[jp][0], bh[jp][1], bh[jp + 1][0], bh[jp + 1][1],
                      sb_h + b_off + jp * 640 + kk * 32);
                if (TERMS >= 2)
                    ldsm4(bl[jp][0], bl[jp][1], bl[jp + 1][0], bl[jp + 1][1],
                          sb_l + b_off + jp * 640 + kk * 32);
            }
#pragma unroll
            for (int i = 0; i < 4; i++)
#pragma unroll
                for (int j = 0; j < 8; j++) {
                    mma16816(acc[i][j], ah[i], bh[j][0], bh[j][1]);
                    if (TERMS >= 2)
                        mma16816(acc[i][j], ah[i], bl[j][0], bl[j][1]);
                    if (TERMS == 3)
                        mma16816(acc[i][j], alr[i], bh[j][0], bh[j][1]);
                }
        }
        if (++sidx >= NST) sidx = 0;
    }

    // ---- epilogue
#pragma unroll
    for (int i = 0; i < 4; i++) {
        const int row0 = bm + wm * 64 + i * 16 + (lane >> 2);
        const size_t b0 = (size_t)blockIdx.z * sC + (size_t)row0 * N;
        const size_t b1 = b0 + (size_t)8 * N;
#pragma unroll
        for (int j = 0; j < 8; j++) {
            const int col = bn + wn * 64 + j * 8 + 2 * (lane & 3);
            float c0 = acc[i][j][0], c1 = acc[i][j][1];
            float c2 = acc[i][j][2], c3 = acc[i][j][3];
            if (BIAS) {
                const float bb0 = bias[col], bb1 = bias[col + 1];
                c0 += bb0; c1 += bb1; c2 += bb0; c3 += bb1;
            }
            if (RELU) {
                c0 = fmaxf(c0, 0.f); c1 = fmaxf(c1, 0.f);
                c2 = fmaxf(c2, 0.f); c3 = fmaxf(c3, 0.f);
            }
            if (OUTM == 0) {
                *(float2*)(Cf + b0 + col) = make_float2(c0, c1);
                *(float2*)(Cf + b1 + col) = make_float2(c2, c3);
            } else {
                __half h0 = __float2half_rn(c0), h1 = __float2half_rn(c1);
                __half h2 = __float2half_rn(c2), h3 = __float2half_rn(c3);
                *(__half2*)(Ch + b0 + col) = __halves2half2(h0, h1);
                *(__half2*)(Ch + b1 + col) = __halves2half2(h2, h3);
                if (OUTM == 1) {
                    __half l0 = __float2half_rn(c0 - __half2float(h0));
                    __half l1 = __float2half_rn(c1 - __half2float(h1));
                    __half l2 = __float2half_rn(c2 - __half2float(h2));
                    __half l3 = __float2half_rn(c3 - __half2float(h3));
                    *(__half2*)(Cl + b0 + col) = __halves2half2(l0, l1);
                    *(__half2*)(Cl + b1 + col) = __halves2half2(l2, l3);
                }
            }
        }
    }
}

// ---------------------------------------------------------------------------
// Elementwise fp32 -> (hi, lo) fp16 split.
// ---------------------------------------------------------------------------
__global__ void __launch_bounds__(256) split_kernel(
    const float* __restrict__ in, __half* __restrict__ oh,
    __half* __restrict__ ol)
{
    const size_t idx = (size_t)blockIdx.x * 256 + threadIdx.x;
    float4 v = ((const float4*)in)[idx];
    __half h0 = __float2half_rn(v.x), h1 = __float2half_rn(v.y);
    __half h2 = __float2half_rn(v.z), h3 = __float2half_rn(v.w);
    __half l0 = __float2half_rn(v.x - __half2float(h0));
    __half l1 = __float2half_rn(v.y - __half2float(h1));
    __half l2 = __float2half_rn(v.z - __half2float(h2));
    __half l3 = __float2half_rn(v.w - __half2float(h3));
    ((__half2*)oh)[idx * 2]     = __halves2half2(h0, h1);
    ((__half2*)oh)[idx * 2 + 1] = __halves2half2(h2, h3);
    ((__half2*)ol)[idx * 2]     = __halves2half2(l0, l1);
    ((__half2*)ol)[idx * 2 + 1] = __halves2half2(l2, l3);
}

// ---------------------------------------------------------------------------
// Transpose + split: fp32 in[R][C] -> oh/ol [C][R] fp16
// ---------------------------------------------------------------------------
__global__ void __launch_bounds__(256) transpose_split_kernel(
    const float* __restrict__ in, __half* __restrict__ oh,
    __half* __restrict__ ol, int R, int C)
{
    __shared__ float t[32][33];
    const int c0 = blockIdx.x * 32, r0 = blockIdx.y * 32;
    const int tx = threadIdx.x & 31, ty = threadIdx.x >> 5;
#pragma unroll
    for (int j = 0; j < 4; j++)
        t[ty + j * 8][tx] = in[(size_t)(r0 + ty + j * 8) * C + c0 + tx];
    __syncthreads();
#pragma unroll
    for (int j = 0; j < 4; j++) {
        float v = t[tx][ty + j * 8];
        __half h = __float2half_rn(v);
        __half l = __float2half_rn(v - __half2float(h));
        size_t o = (size_t)(c0 + ty + j * 8) * R + r0 + tx;
        oh[o] = h;
        ol[o] = l;
    }
}

// ---------------------------------------------------------------------------
// Transpose + convert: fp32 in[R][C] -> fp16 out[C][R] (hi only)
// ---------------------------------------------------------------------------
__global__ void __launch_bounds__(256) transpose_convert_kernel(
    const float* __restrict__ in, __half* __restrict__ oh, int R, int C)
{
    __shared__ float t[32][33];
    const int c0 = blockIdx.x * 32, r0 = blockIdx.y * 32;
    const int tx = threadIdx.x & 31, ty = threadIdx.x >> 5;
#pragma unroll
    for (int j = 0; j < 4; j++)
        t[ty + j * 8][tx] = in[(size_t)(r0 + ty + j * 8) * C + c0 + tx];
    __syncthreads();
#pragma unroll
    for (int j = 0; j < 4; j++) {
        size_t o = (size_t)(c0 + ty + j * 8) * R + r0 + tx;
        oh[o] = __float2half_rn(t[tx][ty + j * 8]);
    }
}

// ---------------------------------------------------------------------------
// Transpose fp16 single: ih [R][C] -> oh [C][R], batched via blockIdx.z
// ---------------------------------------------------------------------------
__global__ void __launch_bounds__(256) transpose_half_kernel(
    const __half* __restrict__ ih, __half* __restrict__ oh,
    int R, int C, size_t sin, size_t sout)
{
    __shared__ __half th[32][33];
    ih += (size_t)blockIdx.z * sin;
    oh += (size_t)blockIdx.z * sout;
    const int c0 = blockIdx.x * 32, r0 = blockIdx.y * 32;
    const int tx = threadIdx.x & 31, ty = threadIdx.x >> 5;
#pragma unroll
    for (int j = 0; j < 4; j++)
        th[ty + j * 8][tx] = ih[(size_t)(r0 + ty + j * 8) * C + c0 + tx];
    __syncthreads();
#pragma unroll
    for (int j = 0; j < 4; j++)
        oh[(size_t)(c0 + ty + j * 8) * R + r0 + tx] = th[tx][ty + j * 8];
}

// ---------------------------------------------------------------------------
// Per-batch deterministic mask scan: active q indices + count.
// ---------------------------------------------------------------------------
__global__ void __launch_bounds__(256) mask_scan_kernel(
    const int* __restrict__ qmask, int* __restrict__ idx, int* __restrict__ nq)
{
    const int b = blockIdx.x;
    const int* m = qmask + (size_t)b * QD;
    __shared__ int cnt[256];
    const int tid = threadIdx.x;

    int loc[8];
    int c = 0;
#pragma unroll
    for (int j = 0; j < 8; j++) {
        loc[j] = m[tid * 8 + j];
        c += loc[j];
    }
    cnt[tid] = c;
    __syncthreads();
    for (int off = 1; off < 256; off <<= 1) {
        int v = (tid >= off) ? cnt[tid - off] : 0;
        __syncthreads();
        cnt[tid] += v;
        __syncthreads();
    }
    int base = cnt[tid] - c;   // exclusive
#pragma unroll
    for (int j = 0; j < 8; j++) {
        if (loc[j]) {
            if (base < NQPAD) idx[(size_t)b * QD + base] = tid * 8 + j;
            base++;
        }
    }
    if (tid == 255) nq[b] = cnt[255] < NQPAD ? cnt[255] : NQPAD;
}

// ---------------------------------------------------------------------------
// Gather active question rows + split to fp16 pair; pad rows -> zeros.
// ---------------------------------------------------------------------------
__global__ void __launch_bounds__(256) gather_split_kernel(
    const float* __restrict__ question, const int* __restrict__ idx,
    const int* __restrict__ nq, __half* __restrict__ oh, __half* __restrict__ ol)
{
    const int r = blockIdx.x % NQPAD;
    const int b = blockIdx.x / NQPAD;
    const int tid = threadIdx.x;
    const size_t dst = ((size_t)b * NQPAD + r) * DD + tid * 4;

    if (r < nq[b]) {
        const int src_row = idx[(size_t)b * QD + r];
        float4 v = *(const float4*)(question + ((size_t)b * QD + src_row) * DD + tid * 4);
        __half h0 = __float2half_rn(v.x), h1 = __float2half_rn(v.y);
        __half h2 = __float2half_rn(v.z), h3 = __float2half_rn(v.w);
        __half l0 = __float2half_rn(v.x - __half2float(h0));
        __half l1 = __float2half_rn(v.y - __half2float(h1));
        __half l2 = __float2half_rn(v.z - __half2float(h2));
        __half l3 = __float2half_rn(v.w - __half2float(h3));
        *(__half2*)(oh + dst)     = __halves2half2(h0, h1);
        *(__half2*)(oh + dst + 2) = __halves2half2(h2, h3);
        *(__half2*)(ol + dst)     = __halves2half2(l0, l1);
        *(__half2*)(ol + dst + 2) = __halves2half2(l2, l3);
    } else {
        *(float2*)(oh + dst) = make_float2(0.f, 0.f);
        *(float2*)(ol + dst) = make_float2(0.f, 0.f);
    }
}

// ---------------------------------------------------------------------------
// Softmax over compacted rows S[BP, NQPAD], active cols = nq[b].
// Writes fp16 alpha (no low part — consumed by 1-term GEMM).
// ---------------------------------------------------------------------------
#define SMX_IT ((NQPAD + 255) / 256)   // 5
__global__ void __launch_bounds__(256) softmax_kernel(
    const float* __restrict__ S, const int* __restrict__ nq_arr,
    __half* __restrict__ ah)
{
    const size_t row = blockIdx.x;
    const int b = (int)(row / PD);
    const float* s = S + row * NQPAD;
    const int nq = nq_arr[b];

    __shared__ float red[256];
    const int tid = threadIdx.x;

    float vals[SMX_IT];
    float m = -INFINITY;
#pragma unroll
    for (int i = 0; i < SMX_IT; i++) {
        int qq = tid + i * 256;
        vals[i] = (qq < NQPAD) ? s[qq] : 0.f;
        if (qq < nq) m = fmaxf(m, vals[i]);
    }
    red[tid] = m;
    __syncthreads();
    for (int st = 128; st > 0; st >>= 1) {
        if (tid < st) red[tid] = fmaxf(red[tid], red[tid + st]);
        __syncthreads();
    }
    m = red[0];
    __syncthreads();

    float sum = 0.f;
#pragma unroll
    for (int i = 0; i < SMX_IT; i++) {
        int qq = tid + i * 256;
        float e = (qq < nq) ? expf(vals[i] - m) : 0.f;
        vals[i] = e;
        sum += e;
    }
    red[tid] = sum;
    __syncthreads();
    for (int st = 128; st > 0; st >>= 1) {
        if (tid < st) red[tid] += red[tid + st];
        __syncthreads();
    }
    sum = red[0];

    const float inv = (sum > 0.f) ? (1.f / sum) : 0.f;
#pragma unroll
    for (int i = 0; i < SMX_IT; i++) {
        int qq = tid + i * 256;
        if (qq < NQPAD)
            ah[row * NQPAD + qq] = __float2half_rn(vals[i] * inv);
    }
}

// ---------------------------------------------------------------------------
extern "C" void kernel_launch(void* const* d_in, const int* in_sizes, int n_in,
                              void* d_out, int out_size)
{
    const float* passage  = (const float*)d_in[0];  // [B,P,D]
    const float* question = (const float*)d_in[1];  // [B,Q,D]
    const int*   q_mask   = (const int*)  d_in[2];  // [B,Q]
    const float* W_w      = (const float*)d_in[3];  // [D,H]
    const float* W_b      = (const float*)d_in[4];  // [H]
    const float* map_w    = (const float*)d_in[5];  // [H,H]
    const float* map_b    = (const float*)d_in[6];  // [H]
    float* out = (float*)d_out;                     // [B,P,H]

    __half *pass_h, *pass_l, *qc_h, *qc_l, *Wt_h, *Wt_l, *mT_h;
    __half *Wp_h, *Wp_l, *Wq_h, *Wq_l, *WqT_h, *al_h, *O_h;
    float* S;
    int *idx, *nq;
    cudaGetSymbolAddress((void**)&pass_h, g_pass_h);
    cudaGetSymbolAddress((void**)&pass_l, g_pass_l);
    cudaGetSymbolAddress((void**)&qc_h, g_qc_h);
    cudaGetSymbolAddress((void**)&qc_l, g_qc_l);
    cudaGetSymbolAddress((void**)&Wt_h, g_Wt_h);
    cudaGetSymbolAddress((void**)&Wt_l, g_Wt_l);
    cudaGetSymbolAddress((void**)&mT_h, g_mT_h);
    cudaGetSymbolAddress((void**)&Wp_h, g_Wp_h);
    cudaGetSymbolAddress((void**)&Wp_l, g_Wp_l);
    cudaGetSymbolAddress((void**)&Wq_h, g_Wq_h);
    cudaGetSymbolAddress((void**)&Wq_l, g_Wq_l);
    cudaGetSymbolAddress((void**)&WqT_h, g_WqT_h);
    cudaGetSymbolAddress((void**)&S, g_S);
    cudaGetSymbolAddress((void**)&al_h, g_al_h);
    cudaGetSymbolAddress((void**)&O_h, g_O_h);
    cudaGetSymbolAddress((void**)&idx, g_idx);
    cudaGetSymbolAddress((void**)&nq, g_nq);

    static bool attr_set = false;
    if (!attr_set) {
        cudaFuncSetAttribute((const void*)hgemm_kernel<128, 256, 3, 1, true, false>,
                             cudaFuncAttributeMaxDynamicSharedMemorySize,
                             GemmCfg<128, 256, 3>::SMEM);
        cudaFuncSetAttribute((const void*)hgemm_kernel<256, 128, 3, 0, false, false>,
                             cudaFuncAttributeMaxDynamicSharedMemorySize,
                             GemmCfg<256, 128, 3>::SMEM);
        cudaFuncSetAttribute((const void*)hgemm_kernel<128, 256, 1, 2, false, false>,
                             cudaFuncAttributeMaxDynamicSharedMemorySize,
                             GemmCfg<128, 256, 1>::SMEM);
        cudaFuncSetAttribute((const void*)hgemm_kernel<128, 256, 1, 0, true, true>,
                             cudaFuncAttributeMaxDynamicSharedMemorySize,
                             GemmCfg<128, 256, 1>::SMEM);
        attr_set = true;
    }

    dim3 blk(256);

    // mask scan + compact gather of question (split)
    mask_scan_kernel<<<BD, blk>>>(q_mask, idx, nq);
    gather_split_kernel<<<BD * NQPAD, blk>>>(question, idx, nq, qc_h, qc_l);

    // passage split; transposed weights (W_w split, map_w hi-only)
    split_kernel<<<(BP * (size_t)DD) / 1024, blk>>>(passage, pass_h, pass_l);
    transpose_split_kernel<<<dim3(HD / 32, DD / 32), blk>>>(W_w, Wt_h, Wt_l, DD, HD);
    transpose_convert_kernel<<<dim3(HD / 32, HD / 32), blk>>>(map_w, mT_h, HD, HD);

    // Wp = passage @ W_w + W_b  -> split out  [BP, H]   (3-term, score path)
    hgemm_kernel<128, 256, 3, 1, true, false>
        <<<dim3(HD / 256, BP / 128, 1), blk, GemmCfg<128, 256, 3>::SMEM>>>(
        pass_h, pass_l, Wt_h, Wt_l, W_b, nullptr, Wp_h, Wp_l, DD, HD, 0, 0, 0);

    // Wq' = qc @ W_w + W_b -> split out  [B*NQPAD, H]   (3-term, score path)
    hgemm_kernel<128, 256, 3, 1, true, false>
        <<<dim3(HD / 256, (BD * NQPAD) / 128, 1), blk, GemmCfg<128, 256, 3>::SMEM>>>(
        qc_h, qc_l, Wt_h, Wt_l, W_b, nullptr, Wq_h, Wq_l, DD, HD, 0, 0, 0);

    // WqT'[b] = Wq'_h[b]^T  [H, NQPAD]  (hi only — O GEMM is 1-term)
    transpose_half_kernel<<<dim3(HD / 32, NQPAD / 32, BD), blk>>>(
        Wq_h, WqT_h, NQPAD, HD, (size_t)NQPAD * HD, (size_t)HD * NQPAD);

    // S'[b] = Wp[b] @ Wq'[b]^T  -> fp32  [P, NQPAD]  (3-term, 256x128 tiles)
    hgemm_kernel<256, 128, 3, 0, false, false>
        <<<dim3(NQPAD / 128, PD / 256, BD), blk, GemmCfg<256, 128, 3>::SMEM>>>(
        Wp_h, Wp_l, Wq_h, Wq_l, nullptr, S, nullptr, nullptr, HD, NQPAD,
        (size_t)PD * HD, (size_t)NQPAD * HD, (size_t)PD * NQPAD);

    // softmax over active cols -> fp16 alpha
    softmax_kernel<<<BP, blk>>>(S, nq, al_h);

    // O[b] = alpha'[b] @ Wq'[b]  -> fp16 O  [P, H]   (1-term)
    hgemm_kernel<128, 256, 1, 2, false, false>
        <<<dim3(HD / 256, PD / 128, BD), blk, GemmCfg<128, 256, 1>::SMEM>>>(
        al_h, nullptr, WqT_h, nullptr, nullptr, nullptr, O_h, nullptr, NQPAD, HD,
        (size_t)PD * NQPAD, (size_t)HD * NQPAD, (size_t)PD * HD);

    // out = relu(O @ map_w + map_b) -> fp32 d_out   (1-term)
    hgemm_kernel<128, 256, 1, 0, true, true>
        <<<dim3(HD / 256, BP / 128, 1), blk, GemmCfg<128, 256, 1>::SMEM>>>(
        O_h, nullptr, mT_h, nullptr, map_b, out, nullptr, nullptr, HD, HD, 0, 0, 0);
}

// round 16
// speedup vs baseline: 4.8217x; 1.0002x over previous
#include <cuda_runtime.h>
#include <cuda_fp16.h>
#include <math.h>
#include <stdint.h>

// Problem dims (fixed)
#define BD 16
#define PD 2048
#define QD 2048
#define DD 1024
#define HD 1024
#define BP (BD * PD)   // 32768
#define NQPAD 1152     // compacted question length, padded (9 * 128)

// ---------------------------------------------------------------------------
// Scratch (allocation-free: __device__ globals)
// ---------------------------------------------------------------------------
__device__ __half g_pass_h [(size_t)BP * DD];           // passage split
__device__ __half g_pass_l [(size_t)BP * DD];
__device__ __half g_qc_h   [(size_t)BD * NQPAD * DD];   // compacted question split
__device__ __half g_qc_l   [(size_t)BD * NQPAD * DD];
__device__ __half g_Wt_h   [(size_t)HD * DD];           // W_w^T split
__device__ __half g_Wt_l   [(size_t)HD * DD];
__device__ __half g_mT_h   [(size_t)HD * HD];           // map_w^T (fp16 hi only)
__device__ __half g_Wp_h   [(size_t)BP * HD];
__device__ __half g_Wp_l   [(size_t)BP * HD];
__device__ __half g_Wq_h   [(size_t)BD * NQPAD * HD];   // compacted Wq split
__device__ __half g_Wq_l   [(size_t)BD * NQPAD * HD];
__device__ __half g_WqT_h  [(size_t)BD * HD * NQPAD];   // transposed hi only
__device__ float  g_S      [(size_t)BP * NQPAD];        // 151 MB
__device__ __half g_al_h   [(size_t)BP * NQPAD];        // alpha (fp16 only)
__device__ __half g_O_h    [(size_t)BP * HD];           // O (fp16 only)
__device__ int    g_idx    [(size_t)BD * QD];
__device__ int    g_nq     [BD];

// ---------------------------------------------------------------------------
// PTX helpers (all Ampere-era: no arch-suffix gating)
// ---------------------------------------------------------------------------
__device__ __forceinline__ uint32_t smem_u32(const void* p) {
    uint32_t a;
    asm("{ .reg .u64 t; cvta.to.shared.u64 t, %1; cvt.u32.u64 %0, t; }"
        : "=r"(a) : "l"(p));
    return a;
}

__device__ __forceinline__ void cp_async16(uint32_t dst, const void* src) {
    asm volatile("cp.async.cg.shared.global [%0], [%1], 16;"
                 :: "r"(dst), "l"(src));
}
#define CP_COMMIT() asm volatile("cp.async.commit_group;")
template <int N>
__device__ __forceinline__ void cp_wait() {
    asm volatile("cp.async.wait_group %0;" :: "n"(N));
}

__device__ __forceinline__ void ldsm4(uint32_t& r0, uint32_t& r1,
                                      uint32_t& r2, uint32_t& r3, uint32_t addr) {
    asm volatile("ldmatrix.sync.aligned.m8n8.x4.shared.b16 {%0,%1,%2,%3}, [%4];"
                 : "=r"(r0), "=r"(r1), "=r"(r2), "=r"(r3) : "r"(addr));
}

__device__ __forceinline__ void mma16816(float c[4], const uint32_t a[4],
                                         uint32_t b0, uint32_t b1) {
    asm volatile(
        "mma.sync.aligned.m16n8k16.row.col.f32.f16.f16.f32 "
        "{%0,%1,%2,%3}, {%4,%5,%6,%7}, {%8,%9}, {%0,%1,%2,%3};"
        : "+f"(c[0]), "+f"(c[1]), "+f"(c[2]), "+f"(c[3])
        : "r"(a[0]), "r"(a[1]), "r"(a[2]), "r"(a[3]), "r"(b0), "r"(b1));
}

// ---------------------------------------------------------------------------
// HGEMM split-fp16: C[M,N] = A[M,K] * B[N,K]^T  (NT, K-major fp16)
// TERMS=3: ah*bh + ah*bl + al*bh   TERMS=2: ah*bh + ah*bl   TERMS=1: ah*bh
// OUTM: 0 = fp32, 1 = split (h+l), 2 = fp16 h only
// TRIM: 0 none; 1 = skip M-blocks beyond ceil128(nq[b]) (batches packed along
//       M with NQPAD stride); 2 = skip N-blocks beyond ceil128(nq[z]);
//       3 = dynamic K bound ceil32(nq[z]).
// Block BM x BN, 256 threads, warp tile 64x64, K-block 32.
// ---------------------------------------------------------------------------
template <int BM, int BN, int TERMS>
struct GemmCfg {
    static constexpr int AP = (TERMS == 3 ? 2 : 1);   // A parts in smem
    static constexpr int BPP = (TERMS >= 2 ? 2 : 1);  // B parts in smem
    static constexpr int SBYTES = (AP * BM + BPP * BN) * 80;
    static constexpr int NST = (TERMS == 3 ? 3 : 4);
    static constexpr int SMEM = SBYTES * NST;
};

template <int BM, int BN, int TERMS>
__device__ __forceinline__ void stage_load(
    uint32_t sbase, const __half* Ahb, const __half* Alb,
    const __half* Bhb, const __half* Blb, int kb, int K, int tid)
{
    constexpr int AP  = GemmCfg<BM, BN, TERMS>::AP;
    constexpr int BPP = GemmCfg<BM, BN, TERMS>::BPP;
    constexpr int NA  = AP * BM * 4;
    constexpr int TOT = NA + BPP * BN * 4;
#pragma unroll
    for (int u = 0; u < TOT / 256; u++) {
        int i = tid + u * 256;
        const __half* src;
        uint32_t dst;
        if (i < BM * 4) {
            int r = i >> 2, c = i & 3;
            src = Ahb + (size_t)r * K + kb * 32 + c * 8;
            dst = sbase + r * 80 + c * 16;
        } else if (AP == 2 && i < BM * 8) {
            int j = i - BM * 4; int r = j >> 2, c = j & 3;
            src = Alb + (size_t)r * K + kb * 32 + c * 8;
            dst = sbase + BM * 80 + r * 80 + c * 16;
        } else if (i < NA + BN * 4) {
            int j = i - NA; int r = j >> 2, c = j & 3;
            src = Bhb + (size_t)r * K + kb * 32 + c * 8;
            dst = sbase + AP * BM * 80 + r * 80 + c * 16;
        } else {
            int j = i - NA - BN * 4; int r = j >> 2, c = j & 3;
            src = Blb + (size_t)r * K + kb * 32 + c * 8;
            dst = sbase + AP * BM * 80 + BN * 80 + r * 80 + c * 16;
        }
        cp_async16(dst, src);
    }
}

template <int BM, int BN, int TERMS, int OUTM, bool BIAS, bool RELU, int TRIM>
__global__ void __launch_bounds__(256, 1) hgemm_kernel(
    const __half* __restrict__ Ah, const __half* __restrict__ Al,
    const __half* __restrict__ Bh, const __half* __restrict__ Bl,
    const float* __restrict__ bias, const int* __restrict__ nq_arr,
    float* __restrict__ Cf, __half* __restrict__ Ch, __half* __restrict__ Cl,
    int K, int N, size_t sA, size_t sB, size_t sC)
{
    extern __shared__ char smem[];
    const uint32_t smem_base = smem_u32(smem);

    using Cfg = GemmCfg<BM, BN, TERMS>;
    constexpr int SBYTES = Cfg::SBYTES;
    constexpr int NST = Cfg::NST;
    constexpr int AP = Cfg::AP;
    constexpr int WN = BN / 64;         // warps along N
    const int tid  = threadIdx.x;
    const int lane = tid & 31;
    const int wid  = tid >> 5;
    const int wm   = wid / WN;
    const int wn   = wid % WN;
    const int bm   = blockIdx.y * BM;
    const int bn   = blockIdx.x * BN;

    // ---- pad-work trimming (all outputs in trimmed regions are never consumed)
    if (TRIM == 1) {
        int b = bm / NQPAD, lm = bm % NQPAD;
        int nqc = (nq_arr[b] + 127) & ~127;
        if (lm >= nqc) return;
    }
    if (TRIM == 2) {
        int nqc = (nq_arr[blockIdx.z] + 127) & ~127;
        if (bn >= nqc) return;
    }
    int Keff = K;
    if (TRIM == 3) Keff = (nq_arr[blockIdx.z] + 31) & ~31;

    const __half* Ahb = Ah + (size_t)blockIdx.z * sA + (size_t)bm * K;
    const __half* Alb = (TERMS == 3)
        ? Al + (size_t)blockIdx.z * sA + (size_t)bm * K : nullptr;
    const __half* Bhb = Bh + (size_t)blockIdx.z * sB + (size_t)bn * K;
    const __half* Blb = (TERMS >= 2)
        ? Bl + (size_t)blockIdx.z * sB + (size_t)bn * K : nullptr;

    float acc[4][8][4];
#pragma unroll
    for (int i = 0; i < 4; i++)
#pragma unroll
        for (int j = 0; j < 8; j++)
#pragma unroll
            for (int r = 0; r < 4; r++) acc[i][j][r] = 0.f;

    const int nk = Keff / 32;

    // prologue
#pragma unroll
    for (int s = 0; s < NST - 1; s++) {
        stage_load<BM, BN, TERMS>(smem_base + s * SBYTES, Ahb, Alb, Bhb, Blb, s, K, tid);
        CP_COMMIT();
    }

    // lane-invariant fragment offsets
    const uint32_t a_off = (uint32_t)((wm * 64 + (lane & 15)) * 80 + (lane >> 4) * 16);
    const int q = lane >> 3;
    const uint32_t b_off = (uint32_t)((wn * 64 + (q >> 1) * 8 + (lane & 7)) * 80
                                      + (q & 1) * 16);

    int sidx = 0;
    for (int kb = 0; kb < nk; kb++) {
        cp_wait<NST - 2>();
        __syncthreads();

        if (kb + NST - 1 < nk) {
            int ls = sidx + (NST - 1); if (ls >= NST) ls -= NST;
            stage_load<BM, BN, TERMS>(smem_base + ls * SBYTES,
                                      Ahb, Alb, Bhb, Blb, kb + NST - 1, K, tid);
        }
        CP_COMMIT();

        const uint32_t sb = smem_base + sidx * SBYTES;
        const uint32_t sa_h = sb;
        const uint32_t sa_l = sb + BM * 80;            // AP==2 only
        const uint32_t sb_h = sb + AP * BM * 80;
        const uint32_t sb_l = sb_h + BN * 80;          // BPP==2 only

#pragma unroll
        for (int kk = 0; kk < 2; kk++) {
            uint32_t ah[4][4], alr[4][4];
#pragma unroll
            for (int i = 0; i < 4; i++) {
                ldsm4(ah[i][0], ah[i][1], ah[i][2], ah[i][3],
                      sa_h + a_off + i * 1280 + kk * 32);
                if (TERMS == 3)
                    ldsm4(alr[i][0], alr[i][1], alr[i][2], alr[i][3],
                          sa_l + a_off + i * 1280 + kk * 32);
            }
            uint32_t bh[8][2], bl[8][2];
#pragma unroll
            for (int jp = 0; jp < 8; jp += 2) {
                ldsm4(bh[jp][0], bh[jp][1], bh[jp + 1][0], bh[jp + 1][1],
                      sb_h + b_off + jp * 640 + kk * 32);
                if (TERMS >= 2)
                    ldsm4(bl[jp][0], bl[jp][1], bl[jp + 1][0], bl[jp + 1][1],
                          sb_l + b_off + jp * 640 + kk * 32);
            }
#pragma unroll
            for (int i = 0; i < 4; i++)
#pragma unroll
                for (int j = 0; j < 8; j++) {
                    mma16816(acc[i][j], ah[i], bh[j][0], bh[j][1]);
                    if (TERMS >= 2)
                        mma16816(acc[i][j], ah[i], bl[j][0], bl[j][1]);
                    if (TERMS == 3)
                        mma16816(acc[i][j], alr[i], bh[j][0], bh[j][1]);
                }
        }
        if (++sidx >= NST) sidx = 0;
    }

    // ---- epilogue
#pragma unroll
    for (int i = 0; i < 4; i++) {
        const int row0 = bm + wm * 64 + i * 16 + (lane >> 2);
        const size_t b0 = (size_t)blockIdx.z * sC + (size_t)row0 * N;
        const size_t b1 = b0 + (size_t)8 * N;
#pragma unroll
        for (int j = 0; j < 8; j++) {
            const int col = bn + wn * 64 + j * 8 + 2 * (lane & 3);
            float c0 = acc[i][j][0], c1 = acc[i][j][1];
            float c2 = acc[i][j][2], c3 = acc[i][j][3];
            if (BIAS) {
                const float bb0 = bias[col], bb1 = bias[col + 1];
                c0 += bb0; c1 += bb1; c2 += bb0; c3 += bb1;
            }
            if (RELU) {
                c0 = fmaxf(c0, 0.f); c1 = fmaxf(c1, 0.f);
                c2 = fmaxf(c2, 0.f); c3 = fmaxf(c3, 0.f);
            }
            if (OUTM == 0) {
                *(float2*)(Cf + b0 + col) = make_float2(c0, c1);
                *(float2*)(Cf + b1 + col) = make_float2(c2, c3);
            } else {
                __half h0 = __float2half_rn(c0), h1 = __float2half_rn(c1);
                __half h2 = __float2half_rn(c2), h3 = __float2half_rn(c3);
                *(__half2*)(Ch + b0 + col) = __halves2half2(h0, h1);
                *(__half2*)(Ch + b1 + col) = __halves2half2(h2, h3);
                if (OUTM == 1) {
                    __half l0 = __float2half_rn(c0 - __half2float(h0));
                    __half l1 = __float2half_rn(c1 - __half2float(h1));
                    __half l2 = __float2half_rn(c2 - __half2float(h2));
                    __half l3 = __float2half_rn(c3 - __half2float(h3));
                    *(__half2*)(Cl + b0 + col) = __halves2half2(l0, l1);
                    *(__half2*)(Cl + b1 + col) = __halves2half2(l2, l3);
                }
            }
        }
    }
}

// ---------------------------------------------------------------------------
// Elementwise fp32 -> (hi, lo) fp16 split.
// ---------------------------------------------------------------------------
__global__ void __launch_bounds__(256) split_kernel(
    const float* __restrict__ in, __half* __restrict__ oh,
    __half* __restrict__ ol)
{
    const size_t idx = (size_t)blockIdx.x * 256 + threadIdx.x;
    float4 v = ((const float4*)in)[idx];
    __half h0 = __float2half_rn(v.x), h1 = __float2half_rn(v.y);
    __half h2 = __float2half_rn(v.z), h3 = __float2half_rn(v.w);
    __half l0 = __float2half_rn(v.x - __half2float(h0));
    __half l1 = __float2half_rn(v.y - __half2float(h1));
    __half l2 = __float2half_rn(v.z - __half2float(h2));
    __half l3 = __float2half_rn(v.w - __half2float(h3));
    ((__half2*)oh)[idx * 2]     = __halves2half2(h0, h1);
    ((__half2*)oh)[idx * 2 + 1] = __halves2half2(h2, h3);
    ((__half2*)ol)[idx * 2]     = __halves2half2(l0, l1);
    ((__half2*)ol)[idx * 2 + 1] = __halves2half2(l2, l3);
}

// ---------------------------------------------------------------------------
// Transpose + split: fp32 in[R][C] -> oh/ol [C][R] fp16
// ---------------------------------------------------------------------------
__global__ void __launch_bounds__(256) transpose_split_kernel(
    const float* __restrict__ in, __half* __restrict__ oh,
    __half* __restrict__ ol, int R, int C)
{
    __shared__ float t[32][33];
    const int c0 = blockIdx.x * 32, r0 = blockIdx.y * 32;
    const int tx = threadIdx.x & 31, ty = threadIdx.x >> 5;
#pragma unroll
    for (int j = 0; j < 4; j++)
        t[ty + j * 8][tx] = in[(size_t)(r0 + ty + j * 8) * C + c0 + tx];
    __syncthreads();
#pragma unroll
    for (int j = 0; j < 4; j++) {
        float v = t[tx][ty + j * 8];
        __half h = __float2half_rn(v);
        __half l = __float2half_rn(v - __half2float(h));
        size_t o = (size_t)(c0 + ty + j * 8) * R + r0 + tx;
        oh[o] = h;
        ol[o] = l;
    }
}

// ---------------------------------------------------------------------------
// Transpose + convert: fp32 in[R][C] -> fp16 out[C][R] (hi only)
// ---------------------------------------------------------------------------
__global__ void __launch_bounds__(256) transpose_convert_kernel(
    const float* __restrict__ in, __half* __restrict__ oh, int R, int C)
{
    __shared__ float t[32][33];
    const int c0 = blockIdx.x * 32, r0 = blockIdx.y * 32;
    const int tx = threadIdx.x & 31, ty = threadIdx.x >> 5;
#pragma unroll
    for (int j = 0; j < 4; j++)
        t[ty + j * 8][tx] = in[(size_t)(r0 + ty + j * 8) * C + c0 + tx];
    __syncthreads();
#pragma unroll
    for (int j = 0; j < 4; j++) {
        size_t o = (size_t)(c0 + ty + j * 8) * R + r0 + tx;
        oh[o] = __float2half_rn(t[tx][ty + j * 8]);
    }
}

// ---------------------------------------------------------------------------
// Transpose fp16 single: ih [R][C] -> oh [C][R], batched via blockIdx.z
// ---------------------------------------------------------------------------
__global__ void __launch_bounds__(256) transpose_half_kernel(
    const __half* __restrict__ ih, __half* __restrict__ oh,
    int R, int C, size_t sin, size_t sout)
{
    __shared__ __half th[32][33];
    ih += (size_t)blockIdx.z * sin;
    oh += (size_t)blockIdx.z * sout;
    const int c0 = blockIdx.x * 32, r0 = blockIdx.y * 32;
    const int tx = threadIdx.x & 31, ty = threadIdx.x >> 5;
#pragma unroll
    for (int j = 0; j < 4; j++)
        th[ty + j * 8][tx] = ih[(size_t)(r0 + ty + j * 8) * C + c0 + tx];
    __syncthreads();
#pragma unroll
    for (int j = 0; j < 4; j++)
        oh[(size_t)(c0 + ty + j * 8) * R + r0 + tx] = th[tx][ty + j * 8];
}

// ---------------------------------------------------------------------------
// Per-batch deterministic mask scan: active q indices + count.
// ---------------------------------------------------------------------------
__global__ void __launch_bounds__(256) mask_scan_kernel(
    const int* __restrict__ qmask, int* __restrict__ idx, int* __restrict__ nq)
{
    const int b = blockIdx.x;
    const int* m = qmask + (size_t)b * QD;
    __shared__ int cnt[256];
    const int tid = threadIdx.x;

    int loc[8];
    int c = 0;
#pragma unroll
    for (int j = 0; j < 8; j++) {
        loc[j] = m[tid * 8 + j];
        c += loc[j];
    }
    cnt[tid] = c;
    __syncthreads();
    for (int off = 1; off < 256; off <<= 1) {
        int v = (tid >= off) ? cnt[tid - off] : 0;
        __syncthreads();
        cnt[tid] += v;
        __syncthreads();
    }
    int base = cnt[tid] - c;   // exclusive
#pragma unroll
    for (int j = 0; j < 8; j++) {
        if (loc[j]) {
            if (base < NQPAD) idx[(size_t)b * QD + base] = tid * 8 + j;
            base++;
        }
    }
    if (tid == 255) nq[b] = cnt[255] < NQPAD ? cnt[255] : NQPAD;
}

// ---------------------------------------------------------------------------
// Gather active question rows + split to fp16 pair; pad rows -> zeros.
// ---------------------------------------------------------------------------
__global__ void __launch_bounds__(256) gather_split_kernel(
    const float* __restrict__ question, const int* __restrict__ idx,
    const int* __restrict__ nq, __half* __restrict__ oh, __half* __restrict__ ol)
{
    const int r = blockIdx.x % NQPAD;
    const int b = blockIdx.x / NQPAD;
    const int tid = threadIdx.x;
    const size_t dst = ((size_t)b * NQPAD + r) * DD + tid * 4;

    if (r < nq[b]) {
        const int src_row = idx[(size_t)b * QD + r];
        float4 v = *(const float4*)(question + ((size_t)b * QD + src_row) * DD + tid * 4);
        __half h0 = __float2half_rn(v.x), h1 = __float2half_rn(v.y);
        __half h2 = __float2half_rn(v.z), h3 = __float2half_rn(v.w);
        __half l0 = __float2half_rn(v.x - __half2float(h0));
        __half l1 = __float2half_rn(v.y - __half2float(h1));
        __half l2 = __float2half_rn(v.z - __half2float(h2));
        __half l3 = __float2half_rn(v.w - __half2float(h3));
        *(__half2*)(oh + dst)     = __halves2half2(h0, h1);
        *(__half2*)(oh + dst + 2) = __halves2half2(h2, h3);
        *(__half2*)(ol + dst)     = __halves2half2(l0, l1);
        *(__half2*)(ol + dst + 2) = __halves2half2(l2, l3);
    } else {
        *(float2*)(oh + dst) = make_float2(0.f, 0.f);
        *(float2*)(ol + dst) = make_float2(0.f, 0.f);
    }
}

// ---------------------------------------------------------------------------
// Softmax over compacted rows S[BP, NQPAD], active cols = nq[b].
// float4 loads / half2 stores. Writes fp16 alpha; pad cols -> 0.
// Row = 288 float4: thread t handles f4 index t, plus 256+t when t < 32.
// ---------------------------------------------------------------------------
__global__ void __launch_bounds__(256) softmax_kernel(
    const float* __restrict__ S, const int* __restrict__ nq_arr,
    __half* __restrict__ ah)
{
    const size_t row = blockIdx.x;
    const int b = (int)(row / PD);
    const float4* s4 = (const float4*)(S + row * NQPAD);
    const int nq = nq_arr[b];
    const int tid = threadIdx.x;
    __shared__ float red[256];

    float4 v0 = s4[tid];
    const bool has2 = (tid < (NQPAD / 4 - 256));   // tid < 32
    float4 v1 = make_float4(0.f, 0.f, 0.f, 0.f);
    if (has2) v1 = s4[256 + tid];

    const int c0 = tid * 4;
    const int c1 = (256 + tid) * 4;

    float m = -INFINITY;
    if (c0 + 0 < nq) m = fmaxf(m, v0.x);
    if (c0 + 1 < nq) m = fmaxf(m, v0.y);
    if (c0 + 2 < nq) m = fmaxf(m, v0.z);
    if (c0 + 3 < nq) m = fmaxf(m, v0.w);
    if (has2) {
        if (c1 + 0 < nq) m = fmaxf(m, v1.x);
        if (c1 + 1 < nq) m = fmaxf(m, v1.y);
        if (c1 + 2 < nq) m = fmaxf(m, v1.z);
        if (c1 + 3 < nq) m = fmaxf(m, v1.w);
    }
    red[tid] = m;
    __syncthreads();
    for (int st = 128; st > 0; st >>= 1) {
        if (tid < st) red[tid] = fmaxf(red[tid], red[tid + st]);
        __syncthreads();
    }
    m = red[0];
    __syncthreads();

    float e0x = (c0 + 0 < nq) ? expf(v0.x - m) : 0.f;
    float e0y = (c0 + 1 < nq) ? expf(v0.y - m) : 0.f;
    float e0z = (c0 + 2 < nq) ? expf(v0.z - m) : 0.f;
    float e0w = (c0 + 3 < nq) ? expf(v0.w - m) : 0.f;
    float e1x = 0.f, e1y = 0.f, e1z = 0.f, e1w = 0.f;
    if (has2) {
        e1x = (c1 + 0 < nq) ? expf(v1.x - m) : 0.f;
        e1y = (c1 + 1 < nq) ? expf(v1.y - m) : 0.f;
        e1z = (c1 + 2 < nq) ? expf(v1.z - m) : 0.f;
        e1w = (c1 + 3 < nq) ? expf(v1.w - m) : 0.f;
    }
    float sum = (e0x + e0y) + (e0z + e0w) + (e1x + e1y) + (e1z + e1w);
    red[tid] = sum;
    __syncthreads();
    for (int st = 128; st > 0; st >>= 1) {
        if (tid < st) red[tid] += red[tid + st];
        __syncthreads();
    }
    sum = red[0];

    const float inv = (sum > 0.f) ? (1.f / sum) : 0.f;
    __half2* a2 = (__half2*)(ah + row * NQPAD);
    a2[2 * tid]     = __floats2half2_rn(e0x * inv, e0y * inv);
    a2[2 * tid + 1] = __floats2half2_rn(e0z * inv, e0w * inv);
    if (has2) {
        a2[2 * (256 + tid)]     = __floats2half2_rn(e1x * inv, e1y * inv);
        a2[2 * (256 + tid) + 1] = __floats2half2_rn(e1z * inv, e1w * inv);
    }
}

// ---------------------------------------------------------------------------
extern "C" void kernel_launch(void* const* d_in, const int* in_sizes, int n_in,
                              void* d_out, int out_size)
{
    const float* passage  = (const float*)d_in[0];  // [B,P,D]
    const float* question = (const float*)d_in[1];  // [B,Q,D]
    const int*   q_mask   = (const int*)  d_in[2];  // [B,Q]
    const float* W_w      = (const float*)d_in[3];  // [D,H]
    const float* W_b      = (const float*)d_in[4];  // [H]
    const float* map_w    = (const float*)d_in[5];  // [H,H]
    const float* map_b    = (const float*)d_in[6];  // [H]
    float* out = (float*)d_out;                     // [B,P,H]

    __half *pass_h, *pass_l, *qc_h, *qc_l, *Wt_h, *Wt_l, *mT_h;
    __half *Wp_h, *Wp_l, *Wq_h, *Wq_l, *WqT_h, *al_h, *O_h;
    float* S;
    int *idx, *nq;
    cudaGetSymbolAddress((void**)&pass_h, g_pass_h);
    cudaGetSymbolAddress((void**)&pass_l, g_pass_l);
    cudaGetSymbolAddress((void**)&qc_h, g_qc_h);
    cudaGetSymbolAddress((void**)&qc_l, g_qc_l);
    cudaGetSymbolAddress((void**)&Wt_h, g_Wt_h);
    cudaGetSymbolAddress((void**)&Wt_l, g_Wt_l);
    cudaGetSymbolAddress((void**)&mT_h, g_mT_h);
    cudaGetSymbolAddress((void**)&Wp_h, g_Wp_h);
    cudaGetSymbolAddress((void**)&Wp_l, g_Wp_l);
    cudaGetSymbolAddress((void**)&Wq_h, g_Wq_h);
    cudaGetSymbolAddress((void**)&Wq_l, g_Wq_l);
    cudaGetSymbolAddress((void**)&WqT_h, g_WqT_h);
    cudaGetSymbolAddress((void**)&S, g_S);
    cudaGetSymbolAddress((void**)&al_h, g_al_h);
    cudaGetSymbolAddress((void**)&O_h, g_O_h);
    cudaGetSymbolAddress((void**)&idx, g_idx);
    cudaGetSymbolAddress((void**)&nq, g_nq);

    static bool attr_set = false;
    if (!attr_set) {
        cudaFuncSetAttribute((const void*)hgemm_kernel<128, 256, 3, 1, true, false, 0>,
                             cudaFuncAttributeMaxDynamicSharedMemorySize,
                             GemmCfg<128, 256, 3>::SMEM);
        cudaFuncSetAttribute((const void*)hgemm_kernel<128, 256, 3, 1, true, false, 1>,
                             cudaFuncAttributeMaxDynamicSharedMemorySize,
                             GemmCfg<128, 256, 3>::SMEM);
        cudaFuncSetAttribute((const void*)hgemm_kernel<256, 128, 3, 0, false, false, 2>,
                             cudaFuncAttributeMaxDynamicSharedMemorySize,
                             GemmCfg<256, 128, 3>::SMEM);
        cudaFuncSetAttribute((const void*)hgemm_kernel<128, 256, 1, 2, false, false, 3>,
                             cudaFuncAttributeMaxDynamicSharedMemorySize,
                             GemmCfg<128, 256, 1>::SMEM);
        cudaFuncSetAttribute((const void*)hgemm_kernel<128, 256, 1, 0, true, true, 0>,
                             cudaFuncAttributeMaxDynamicSharedMemorySize,
                             GemmCfg<128, 256, 1>::SMEM);
        attr_set = true;
    }

    dim3 blk(256);

    // mask scan + compact gather of question (split)
    mask_scan_kernel<<<BD, blk>>>(q_mask, idx, nq);
    gather_split_kernel<<<BD * NQPAD, blk>>>(question, idx, nq, qc_h, qc_l);

    // passage split; transposed weights (W_w split, map_w hi-only)
    split_kernel<<<(BP * (size_t)DD) / 1024, blk>>>(passage, pass_h, pass_l);
    transpose_split_kernel<<<dim3(HD / 32, DD / 32), blk>>>(W_w, Wt_h, Wt_l, DD, HD);
    transpose_convert_kernel<<<dim3(HD / 32, HD / 32), blk>>>(map_w, mT_h, HD, HD);

    // Wp = passage @ W_w + W_b  -> split out  [BP, H]   (3-term)
    hgemm_kernel<128, 256, 3, 1, true, false, 0>
        <<<dim3(HD / 256, BP / 128, 1), blk, GemmCfg<128, 256, 3>::SMEM>>>(
        pass_h, pass_l, Wt_h, Wt_l, W_b, nullptr,
        nullptr, Wp_h, Wp_l, DD, HD, 0, 0, 0);

    // Wq' = qc @ W_w + W_b -> split out  [B*NQPAD, H]   (3-term, M-trimmed)
    hgemm_kernel<128, 256, 3, 1, true, false, 1>
        <<<dim3(HD / 256, (BD * NQPAD) / 128, 1), blk, GemmCfg<128, 256, 3>::SMEM>>>(
        qc_h, qc_l, Wt_h, Wt_l, W_b, nq,
        nullptr, Wq_h, Wq_l, DD, HD, 0, 0, 0);

    // WqT'[b] = Wq'_h[b]^T  [H, NQPAD]  (hi only — O GEMM is 1-term)
    transpose_half_kernel<<<dim3(HD / 32, NQPAD / 32, BD), blk>>>(
        Wq_h, WqT_h, NQPAD, HD, (size_t)NQPAD * HD, (size_t)HD * NQPAD);

    // S'[b] = Wp[b] @ Wq'[b]^T  -> fp32  [P, NQPAD]  (3-term, N-trimmed)
    hgemm_kernel<256, 128, 3, 0, false, false, 2>
        <<<dim3(NQPAD / 128, PD / 256, BD), blk, GemmCfg<256, 128, 3>::SMEM>>>(
        Wp_h, Wp_l, Wq_h, Wq_l, nullptr, nq,
        S, nullptr, nullptr, HD, NQPAD,
        (size_t)PD * HD, (size_t)NQPAD * HD, (size_t)PD * NQPAD);

    // softmax over active cols -> fp16 alpha (vectorized)
    softmax_kernel<<<BP, blk>>>(S, nq, al_h);

    // O[b] = alpha'[b] @ Wq'[b]  -> fp16 O  [P, H]   (1-term, dynamic K)
    hgemm_kernel<128, 256, 1, 2, false, false, 3>
        <<<dim3(HD / 256, PD / 128, BD), blk, GemmCfg<128, 256, 1>::SMEM>>>(
        al_h, nullptr, WqT_h, nullptr, nullptr, nq,
        nullptr, O_h, nullptr, NQPAD, HD,
        (size_t)PD * NQPAD, (size_t)HD * NQPAD, (size_t)PD * HD);

    // out = relu(O @ map_w + map_b) -> fp32 d_out   (1-term)
    hgemm_kernel<128, 256, 1, 0, true, true, 0>
        <<<dim3(HD / 256, BP / 128, 1), blk, GemmCfg<128, 256, 1>::SMEM>>>(
        O_h, nullptr, mT_h, nullptr, map_b, nullptr,
        out, nullptr, nullptr, HD, HD, 0, 0, 0);
}